// round 4
// baseline (speedup 1.0000x reference)
#include <cuda_runtime.h>
#include <cuda_bf16.h>
#include <stdint.h>
#include <math.h>

#define Tn 4096
#define Hn 1024
#define En 8
#define In 1024

// ==================== scratch ====================
__device__ int   g_cnt[En];
__device__ float g_imp[En];
__device__ int   g_tk [Tn * 2];
__device__ float g_tkw[Tn * 2];
// pre-split weights, TRANSPOSED to [E][N][K]
__device__ __nv_bfloat16 g_wg_h[(size_t)En * In * Hn], g_wg_l[(size_t)En * In * Hn];
__device__ __nv_bfloat16 g_wu_h[(size_t)En * In * Hn], g_wu_l[(size_t)En * In * Hn];
__device__ __nv_bfloat16 g_wd_h[(size_t)En * Hn * In], g_wd_l[(size_t)En * Hn * In];
// pre-gathered split activations per (expert,pos) slot
__device__ __nv_bfloat16 g_xa_h[(size_t)En * Tn * Hn], g_xa_l[(size_t)En * Tn * Hn];
// split intermediate
__device__ __nv_bfloat16 g_ih[(size_t)En * Tn * In], g_il[(size_t)En * Tn * In];
// per-slot expert output
__device__ float g_out2[(size_t)En * Tn * Hn];

// ==================== helpers ====================
__device__ __forceinline__ uint32_t smem_u32(const void* p) {
    uint32_t a;
    asm("{ .reg .u64 t; cvta.to.shared.u64 t, %1; cvt.u32.u64 %0, t; }" : "=r"(a) : "l"(p));
    return a;
}
__device__ __forceinline__ void cpa16(uint32_t dst, const void* src) {
    asm volatile("cp.async.cg.shared.global [%0], [%1], 16;" :: "r"(dst), "l"(src));
}
#define CP_COMMIT() asm volatile("cp.async.commit_group;" ::: "memory")
#define CP_WAIT3()  asm volatile("cp.async.wait_group 3;" ::: "memory")

#define LDM4(r, addr)                                                          \
    asm volatile("ldmatrix.sync.aligned.m8n8.x4.shared.b16 {%0,%1,%2,%3}, [%4];" \
        : "=r"((r)[0]), "=r"((r)[1]), "=r"((r)[2]), "=r"((r)[3]) : "r"(addr))

#define MMA(d, a, b0, b1)                                                      \
    asm volatile("mma.sync.aligned.m16n8k16.row.col.f32.bf16.bf16.f32 "        \
        "{%0,%1,%2,%3}, {%4,%5,%6,%7}, {%8,%9}, {%0,%1,%2,%3};"                \
        : "+f"((d)[0]), "+f"((d)[1]), "+f"((d)[2]), "+f"((d)[3])               \
        : "r"((a)[0]), "r"((a)[1]), "r"((a)[2]), "r"((a)[3]), "r"(b0), "r"(b1))

__device__ __forceinline__ void split2(float a, float b, uint32_t& hi, uint32_t& lo) {
    __nv_bfloat16 ha = __float2bfloat16(a), hb = __float2bfloat16(b);
    float ra = a - __bfloat162float(ha);
    float rb = b - __bfloat162float(hb);
    __nv_bfloat162 H; H.x = ha; H.y = hb;
    __nv_bfloat162 L = __floats2bfloat162_rn(ra, rb);
    hi = *(uint32_t*)&H;  lo = *(uint32_t*)&L;
}

// ==================== small kernels ====================
__global__ void init_kernel() {
    if (threadIdx.x < En) { g_cnt[threadIdx.x] = 0; g_imp[threadIdx.x] = 0.0f; }
}

__global__ void router_kernel(const float* __restrict__ x, const float* __restrict__ Wr) {
    int t = blockIdx.x;
    int warp = threadIdx.x >> 5, lane = threadIdx.x & 31;
    const float* xt = x + (size_t)t * Hn;
    float acc = 0.0f;
    for (int h = lane; h < Hn; h += 32) acc += xt[h] * Wr[h * En + warp];
    #pragma unroll
    for (int o = 16; o > 0; o >>= 1) acc += __shfl_xor_sync(0xffffffff, acc, o);
    __shared__ float logits[En];
    if (lane == 0) logits[warp] = acc;
    __syncthreads();
    if (threadIdx.x == 0) {
        float mx = logits[0];
        #pragma unroll
        for (int e = 1; e < En; e++) mx = fmaxf(mx, logits[e]);
        float p[En], s = 0.0f;
        #pragma unroll
        for (int e = 0; e < En; e++) { p[e] = expf(logits[e] - mx); s += p[e]; }
        float inv = 1.0f / s;
        #pragma unroll
        for (int e = 0; e < En; e++) { p[e] *= inv; atomicAdd(&g_imp[e], p[e]); }
        int i0 = 0;
        #pragma unroll
        for (int e = 1; e < En; e++) if (p[e] > p[i0]) i0 = e;
        int i1 = (i0 == 0) ? 1 : 0;
        #pragma unroll
        for (int e = 0; e < En; e++) if (e != i0 && p[e] > p[i1]) i1 = e;
        float w0 = p[i0], w1 = p[i1];
        float sw = fmaxf(w0 + w1, 1e-9f);
        w0 /= sw; w1 /= sw;
        int p0 = atomicAdd(&g_cnt[i0], 1);
        int p1 = atomicAdd(&g_cnt[i1], 1);
        g_tk [t * 2]     = i0 * Tn + p0;  g_tkw[t * 2]     = w0;
        g_tk [t * 2 + 1] = i1 * Tn + p1;  g_tkw[t * 2 + 1] = w1;
    }
}

__global__ void aux_kernel(float* out, int aux_idx) {
    if (threadIdx.x == 0) {
        float s = 0.0f;
        #pragma unroll
        for (int e = 0; e < En; e++)
            s += ((float)g_cnt[e] / (float)Tn) * (g_imp[e] / (float)Tn);
        out[aux_idx] = (float)En * s * 0.01f;
    }
}

// transpose + split weights: src [E][K][N] fp32 -> dst [E][N][K] bf16 hi/lo
__global__ void wconv_kernel(const float* __restrict__ Wg,
                             const float* __restrict__ Wu,
                             const float* __restrict__ Wd) {
    int mi = blockIdx.z % 3, e = blockIdx.z / 3;
    const float* src = (mi == 0 ? Wg : (mi == 1 ? Wu : Wd)) + (size_t)e * 1024 * 1024;
    __nv_bfloat16* dh = (mi == 0 ? g_wg_h : (mi == 1 ? g_wu_h : g_wd_h)) + (size_t)e * 1024 * 1024;
    __nv_bfloat16* dl = (mi == 0 ? g_wg_l : (mi == 1 ? g_wu_l : g_wd_l)) + (size_t)e * 1024 * 1024;
    __shared__ float tile[32][33];
    int k0 = blockIdx.x * 32, n0 = blockIdx.y * 32;
    int tx = threadIdx.x & 31, ty = threadIdx.x >> 5;
    #pragma unroll
    for (int i = 0; i < 4; i++) {
        int k = ty + i * 8;
        tile[k][tx] = src[(size_t)(k0 + k) * 1024 + n0 + tx];
    }
    __syncthreads();
    #pragma unroll
    for (int i = 0; i < 4; i++) {
        int n = ty + i * 8;
        float v = tile[tx][n];
        __nv_bfloat16 h = __float2bfloat16(v);
        __nv_bfloat16 l = __float2bfloat16(v - __bfloat162float(h));
        size_t o = (size_t)(n0 + n) * 1024 + k0 + tx;
        dh[o] = h;  dl[o] = l;
    }
}

// gather + split activations into (expert,pos) slots
__global__ void gather_kernel(const float* __restrict__ x) {
    int t = blockIdx.x, which = blockIdx.y;
    int slot = g_tk[2 * t + which];
    const float4* src = (const float4*)(x + (size_t)t * Hn);
    int i = threadIdx.x;                 // 256 threads, 4 floats each
    float4 v = src[i];
    uint32_t h0, l0, h1, l1;
    split2(v.x, v.y, h0, l0);
    split2(v.z, v.w, h1, l1);
    *(uint2*)(g_xa_h + (size_t)slot * Hn + i * 4) = make_uint2(h0, h1);
    *(uint2*)(g_xa_l + (size_t)slot * Hn + i * 4) = make_uint2(l0, l1);
}

__global__ void combine_kernel(float* __restrict__ out) {
    int t = blockIdx.x;
    int s0 = g_tk[2 * t], s1 = g_tk[2 * t + 1];
    float w0 = g_tkw[2 * t], w1 = g_tkw[2 * t + 1];
    const float4* a = (const float4*)(g_out2 + (size_t)s0 * Hn);
    const float4* b = (const float4*)(g_out2 + (size_t)s1 * Hn);
    float4* o = (float4*)(out + (size_t)t * Hn);
    int i = threadIdx.x;
    float4 va = a[i], vb = b[i];
    o[i] = make_float4(w0 * va.x + w1 * vb.x, w0 * va.y + w1 * vb.y,
                       w0 * va.z + w1 * vb.z, w0 * va.w + w1 * vb.w);
}

// ==================== smem layout ====================
#define ROWB 80
#define A_BYTES (128 * ROWB)   // 10240
#define B_BYTES (64 * ROWB)    // 5120
// gemm1 stage: Ah Al | Gh Gl Uh Ul
#define G1_STG (2 * A_BYTES + 4 * B_BYTES)   // 40960
#define G1_SMEM (4 * G1_STG)                 // 163840
// gemm2 stage: Ah Al | Bh Bl
#define G2_STG (2 * A_BYTES + 2 * B_BYTES)   // 30720
#define G2_SMEM (4 * G2_STG)                 // 122880

// ==================== GEMM1 ====================
__device__ __forceinline__ void g1_fill(uint32_t st, int k0, int e, int mBase, int n0, int tid) {
    const __nv_bfloat16* ah = g_xa_h + ((size_t)(e * Tn + mBase)) * Hn + k0;
    const __nv_bfloat16* al = g_xa_l + ((size_t)(e * Tn + mBase)) * Hn + k0;
    #pragma unroll
    for (int it = 0; it < 2; it++) {
        int idx = it * 256 + tid;            // 512 = 128 rows x 4 chunks
        int row = idx >> 2, ch = idx & 3;
        uint32_t doff = row * ROWB + ch * 16;
        cpa16(st + doff,           ah + (size_t)row * Hn + ch * 8);
        cpa16(st + A_BYTES + doff, al + (size_t)row * Hn + ch * 8);
    }
    int row = tid >> 2, ch = tid & 3;        // 256 = 64 rows x 4 chunks
    size_t wo = ((size_t)e * In + n0 + row) * Hn + k0 + ch * 8;
    uint32_t doff = 2 * A_BYTES + row * ROWB + ch * 16;
    cpa16(st + doff,               g_wg_h + wo);
    cpa16(st + B_BYTES + doff,     g_wg_l + wo);
    cpa16(st + 2 * B_BYTES + doff, g_wu_h + wo);
    cpa16(st + 3 * B_BYTES + doff, g_wu_l + wo);
}

__global__ __launch_bounds__(256, 1)
void gemm1_kernel() {
    extern __shared__ char smem[];
    int e = blockIdx.z;
    int n_rows = g_cnt[e];
    int mBase = blockIdx.y * 128;
    if (mBase >= n_rows) return;
    int n0 = blockIdx.x * 64;

    uint32_t sb = smem_u32(smem);
    int tid = threadIdx.x, wid = tid >> 5, lane = tid & 31;
    int wm = wid & 3, wn = wid >> 2;
    int ar = lane & 15, ac = lane >> 4;
    int brow = (lane >> 4) * 8 + (lane & 7);
    int bhalf = (lane & 15) >> 3;

    float aG[2][4][4] = {{{0}}}, aU[2][4][4] = {{{0}}};

    // prologue: stages 0..2
    #pragma unroll
    for (int p = 0; p < 3; p++) {
        g1_fill(sb + p * G1_STG, p * 32, e, mBase, n0, tid);
        CP_COMMIT();
    }

    #pragma unroll 1
    for (int s = 0; s < 32; s++) {
        if (s + 3 < 32) g1_fill(sb + ((s + 3) & 3) * G1_STG, (s + 3) * 32, e, mBase, n0, tid);
        CP_COMMIT();
        CP_WAIT3();
        __syncthreads();

        uint32_t aBase = sb + (s & 3) * G1_STG;
        uint32_t gBase = aBase + 2 * A_BYTES;
        #pragma unroll
        for (int kk = 0; kk < 2; kk++) {
            int kb = kk * 32;
            uint32_t ah[2][4], al[2][4];
            #pragma unroll
            for (int mt = 0; mt < 2; mt++) {
                uint32_t ad = aBase + (uint32_t)(wm * 32 + mt * 16 + ar) * ROWB + kb + ac * 16;
                LDM4(ah[mt], ad);
                LDM4(al[mt], ad + A_BYTES);
            }
            uint32_t bgh[2][4], bgl[2][4], buh[2][4], bul[2][4];
            #pragma unroll
            for (int ng = 0; ng < 2; ng++) {
                uint32_t bd = gBase + (uint32_t)(wn * 32 + ng * 16 + brow) * ROWB + kb + bhalf * 16;
                LDM4(bgh[ng], bd);
                LDM4(bgl[ng], bd + B_BYTES);
                LDM4(buh[ng], bd + 2 * B_BYTES);
                LDM4(bul[ng], bd + 3 * B_BYTES);
            }
            #pragma unroll
            for (int mt = 0; mt < 2; mt++)
                #pragma unroll
                for (int nt = 0; nt < 4; nt++) {
                    int ng = nt >> 1, p = (nt & 1) * 2;
                    MMA(aG[mt][nt], ah[mt], bgh[ng][p], bgh[ng][p + 1]);
                    MMA(aU[mt][nt], ah[mt], buh[ng][p], buh[ng][p + 1]);
                }
            #pragma unroll
            for (int mt = 0; mt < 2; mt++)
                #pragma unroll
                for (int nt = 0; nt < 4; nt++) {
                    int ng = nt >> 1, p = (nt & 1) * 2;
                    MMA(aG[mt][nt], ah[mt], bgl[ng][p], bgl[ng][p + 1]);
                    MMA(aU[mt][nt], ah[mt], bul[ng][p], bul[ng][p + 1]);
                }
            #pragma unroll
            for (int mt = 0; mt < 2; mt++)
                #pragma unroll
                for (int nt = 0; nt < 4; nt++) {
                    int ng = nt >> 1, p = (nt & 1) * 2;
                    MMA(aG[mt][nt], al[mt], bgh[ng][p], bgh[ng][p + 1]);
                    MMA(aU[mt][nt], al[mt], buh[ng][p], buh[ng][p + 1]);
                }
        }
        __syncthreads();
    }

    // epilogue: silu(g)*u -> split bf16 intermediate
    #pragma unroll
    for (int mt = 0; mt < 2; mt++) {
        #pragma unroll
        for (int nt = 0; nt < 4; nt++) {
            int c = n0 + wn * 32 + nt * 8 + (lane & 3) * 2;
            #pragma unroll
            for (int h = 0; h < 2; h++) {
                int r = mBase + wm * 32 + mt * 16 + (lane >> 2) + h * 8;
                if (r < n_rows) {
                    float g0 = aG[mt][nt][h * 2],     u0 = aU[mt][nt][h * 2];
                    float g1 = aG[mt][nt][h * 2 + 1], u1 = aU[mt][nt][h * 2 + 1];
                    float i0 = u0 * g0 / (1.0f + __expf(-g0));
                    float i1 = u1 * g1 / (1.0f + __expf(-g1));
                    uint32_t ph, pl;
                    split2(i0, i1, ph, pl);
                    size_t o = ((size_t)e * Tn + r) * In + c;
                    *(uint32_t*)(g_ih + o) = ph;
                    *(uint32_t*)(g_il + o) = pl;
                }
            }
        }
    }
}

// ==================== GEMM2 ====================
__device__ __forceinline__ void g2_fill(uint32_t st, int k0, int e, int mBase, int n0, int tid) {
    const __nv_bfloat16* ah = g_ih + ((size_t)(e * Tn + mBase)) * In + k0;
    const __nv_bfloat16* al = g_il + ((size_t)(e * Tn + mBase)) * In + k0;
    #pragma unroll
    for (int it = 0; it < 2; it++) {
        int idx = it * 256 + tid;
        int row = idx >> 2, ch = idx & 3;
        uint32_t doff = row * ROWB + ch * 16;
        cpa16(st + doff,           ah + (size_t)row * In + ch * 8);
        cpa16(st + A_BYTES + doff, al + (size_t)row * In + ch * 8);
    }
    int row = tid >> 2, ch = tid & 3;
    size_t wo = ((size_t)e * Hn + n0 + row) * In + k0 + ch * 8;
    uint32_t doff = 2 * A_BYTES + row * ROWB + ch * 16;
    cpa16(st + doff,           g_wd_h + wo);
    cpa16(st + B_BYTES + doff, g_wd_l + wo);
}

__global__ __launch_bounds__(256, 1)
void gemm2_kernel() {
    extern __shared__ char smem[];
    int e = blockIdx.z;
    int n_rows = g_cnt[e];
    int mBase = blockIdx.y * 128;
    if (mBase >= n_rows) return;
    int n0 = blockIdx.x * 64;

    uint32_t sb = smem_u32(smem);
    int tid = threadIdx.x, wid = tid >> 5, lane = tid & 31;
    int wm = wid & 3, wn = wid >> 2;
    int ar = lane & 15, ac = lane >> 4;
    int brow = (lane >> 4) * 8 + (lane & 7);
    int bhalf = (lane & 15) >> 3;

    float acc[2][4][4] = {{{0}}};

    #pragma unroll
    for (int p = 0; p < 3; p++) {
        g2_fill(sb + p * G2_STG, p * 32, e, mBase, n0, tid);
        CP_COMMIT();
    }

    #pragma unroll 1
    for (int s = 0; s < 32; s++) {
        if (s + 3 < 32) g2_fill(sb + ((s + 3) & 3) * G2_STG, (s + 3) * 32, e, mBase, n0, tid);
        CP_COMMIT();
        CP_WAIT3();
        __syncthreads();

        uint32_t aBase = sb + (s & 3) * G2_STG;
        uint32_t bBase = aBase + 2 * A_BYTES;
        #pragma unroll
        for (int kk = 0; kk < 2; kk++) {
            int kb = kk * 32;
            uint32_t ah[2][4], al[2][4];
            #pragma unroll
            for (int mt = 0; mt < 2; mt++) {
                uint32_t ad = aBase + (uint32_t)(wm * 32 + mt * 16 + ar) * ROWB + kb + ac * 16;
                LDM4(ah[mt], ad);
                LDM4(al[mt], ad + A_BYTES);
            }
            uint32_t bh[2][4], bl[2][4];
            #pragma unroll
            for (int ng = 0; ng < 2; ng++) {
                uint32_t bd = bBase + (uint32_t)(wn * 32 + ng * 16 + brow) * ROWB + kb + bhalf * 16;
                LDM4(bh[ng], bd);
                LDM4(bl[ng], bd + B_BYTES);
            }
            #pragma unroll
            for (int mt = 0; mt < 2; mt++)
                #pragma unroll
                for (int nt = 0; nt < 4; nt++) {
                    int ng = nt >> 1, p = (nt & 1) * 2;
                    MMA(acc[mt][nt], ah[mt], bh[ng][p], bh[ng][p + 1]);
                }
            #pragma unroll
            for (int mt = 0; mt < 2; mt++)
                #pragma unroll
                for (int nt = 0; nt < 4; nt++) {
                    int ng = nt >> 1, p = (nt & 1) * 2;
                    MMA(acc[mt][nt], ah[mt], bl[ng][p], bl[ng][p + 1]);
                }
            #pragma unroll
            for (int mt = 0; mt < 2; mt++)
                #pragma unroll
                for (int nt = 0; nt < 4; nt++) {
                    int ng = nt >> 1, p = (nt & 1) * 2;
                    MMA(acc[mt][nt], al[mt], bh[ng][p], bh[ng][p + 1]);
                }
        }
        __syncthreads();
    }

    #pragma unroll
    for (int mt = 0; mt < 2; mt++) {
        #pragma unroll
        for (int nt = 0; nt < 4; nt++) {
            int c = n0 + wn * 32 + nt * 8 + (lane & 3) * 2;
            #pragma unroll
            for (int h = 0; h < 2; h++) {
                int r = mBase + wm * 32 + mt * 16 + (lane >> 2) + h * 8;
                if (r < n_rows)
                    *(float2*)(g_out2 + ((size_t)e * Tn + r) * Hn + c) =
                        make_float2(acc[mt][nt][h * 2], acc[mt][nt][h * 2 + 1]);
            }
        }
    }
}

// ==================== launch ====================
extern "C" void kernel_launch(void* const* d_in, const int* in_sizes, int n_in,
                              void* d_out, int out_size) {
    const float* x  = (const float*)d_in[0];
    const float* Wr = (const float*)d_in[1];
    const float* Wg = (const float*)d_in[2];
    const float* Wu = (const float*)d_in[3];
    const float* Wd = (const float*)d_in[4];
    float* out = (float*)d_out;

    cudaFuncSetAttribute(gemm1_kernel, cudaFuncAttributeMaxDynamicSharedMemorySize, G1_SMEM);
    cudaFuncSetAttribute(gemm2_kernel, cudaFuncAttributeMaxDynamicSharedMemorySize, G2_SMEM);

    init_kernel<<<1, 32>>>();

    dim3 wcg(32, 32, 3 * En);
    wconv_kernel<<<wcg, 256>>>(Wg, Wu, Wd);

    router_kernel<<<Tn, 256>>>(x, Wr);
    if (out_size > Tn * Hn)
        aux_kernel<<<1, 32>>>(out, Tn * Hn);

    dim3 gg(Tn, 2);
    gather_kernel<<<gg, 256>>>(x);

    dim3 g1(In / 64, Tn / 128, En);
    gemm1_kernel<<<g1, 256, G1_SMEM>>>();

    dim3 g2(Hn / 64, Tn / 128, En);
    gemm2_kernel<<<g2, 256, G2_SMEM>>>();

    combine_kernel<<<Tn, 256>>>(out);
}

// round 5
// speedup vs baseline: 1.0245x; 1.0245x over previous
#include <cuda_runtime.h>
#include <cuda_bf16.h>
#include <stdint.h>
#include <math.h>

#define Tn 4096
#define Hn 1024
#define En 8
#define In 1024

// ==================== scratch ====================
__device__ int   g_cnt[En];
__device__ float g_imp[En];
__device__ int   g_tok[En * Tn];
__device__ int   g_tk [Tn * 2];
__device__ float g_tkw[Tn * 2];
// pre-split weights, transposed to [E][N][K], hi/lo
__device__ __nv_bfloat16 g_wg_h[(size_t)En * In * Hn], g_wg_l[(size_t)En * In * Hn];
__device__ __nv_bfloat16 g_wu_h[(size_t)En * In * Hn], g_wu_l[(size_t)En * In * Hn];
__device__ __nv_bfloat16 g_wd_h[(size_t)En * Hn * In], g_wd_l[(size_t)En * Hn * In];
// split intermediate
__device__ __nv_bfloat16 g_ih[(size_t)En * Tn * In], g_il[(size_t)En * Tn * In];
// per-slot expert output
__device__ float g_out2[(size_t)En * Tn * Hn];

// ==================== helpers ====================
__device__ __forceinline__ uint32_t smem_u32(const void* p) {
    uint32_t a;
    asm("{ .reg .u64 t; cvta.to.shared.u64 t, %1; cvt.u32.u64 %0, t; }" : "=r"(a) : "l"(p));
    return a;
}
__device__ __forceinline__ void cpa16(uint32_t dst, const void* src) {
    asm volatile("cp.async.cg.shared.global [%0], [%1], 16;" :: "r"(dst), "l"(src));
}
#define CP_COMMIT() asm volatile("cp.async.commit_group;" ::: "memory")
#define CP_WAIT2()  asm volatile("cp.async.wait_group 2;" ::: "memory")
#define CP_WAIT3()  asm volatile("cp.async.wait_group 3;" ::: "memory")

#define LDM4(r, addr)                                                          \
    asm volatile("ldmatrix.sync.aligned.m8n8.x4.shared.b16 {%0,%1,%2,%3}, [%4];" \
        : "=r"((r)[0]), "=r"((r)[1]), "=r"((r)[2]), "=r"((r)[3]) : "r"(addr))

#define MMA(d, a, b0, b1)                                                      \
    asm volatile("mma.sync.aligned.m16n8k16.row.col.f32.bf16.bf16.f32 "        \
        "{%0,%1,%2,%3}, {%4,%5,%6,%7}, {%8,%9}, {%0,%1,%2,%3};"                \
        : "+f"((d)[0]), "+f"((d)[1]), "+f"((d)[2]), "+f"((d)[3])               \
        : "r"((a)[0]), "r"((a)[1]), "r"((a)[2]), "r"((a)[3]), "r"(b0), "r"(b1))

__device__ __forceinline__ void split2(float a, float b, uint32_t& hi, uint32_t& lo) {
    __nv_bfloat16 ha = __float2bfloat16(a), hb = __float2bfloat16(b);
    float ra = a - __bfloat162float(ha);
    float rb = b - __bfloat162float(hb);
    __nv_bfloat162 H; H.x = ha; H.y = hb;
    __nv_bfloat162 L = __floats2bfloat162_rn(ra, rb);
    hi = *(uint32_t*)&H;  lo = *(uint32_t*)&L;
}

// ==================== small kernels ====================
__global__ void init_kernel() {
    if (threadIdx.x < En) { g_cnt[threadIdx.x] = 0; g_imp[threadIdx.x] = 0.0f; }
}

__global__ void router_kernel(const float* __restrict__ x, const float* __restrict__ Wr) {
    int t = blockIdx.x;
    int warp = threadIdx.x >> 5, lane = threadIdx.x & 31;
    const float* xt = x + (size_t)t * Hn;
    float acc = 0.0f;
    for (int h = lane; h < Hn; h += 32) acc += xt[h] * Wr[h * En + warp];
    #pragma unroll
    for (int o = 16; o > 0; o >>= 1) acc += __shfl_xor_sync(0xffffffff, acc, o);
    __shared__ float logits[En];
    if (lane == 0) logits[warp] = acc;
    __syncthreads();
    if (threadIdx.x == 0) {
        float mx = logits[0];
        #pragma unroll
        for (int e = 1; e < En; e++) mx = fmaxf(mx, logits[e]);
        float p[En], s = 0.0f;
        #pragma unroll
        for (int e = 0; e < En; e++) { p[e] = expf(logits[e] - mx); s += p[e]; }
        float inv = 1.0f / s;
        #pragma unroll
        for (int e = 0; e < En; e++) { p[e] *= inv; atomicAdd(&g_imp[e], p[e]); }
        int i0 = 0;
        #pragma unroll
        for (int e = 1; e < En; e++) if (p[e] > p[i0]) i0 = e;
        int i1 = (i0 == 0) ? 1 : 0;
        #pragma unroll
        for (int e = 0; e < En; e++) if (e != i0 && p[e] > p[i1]) i1 = e;
        float w0 = p[i0], w1 = p[i1];
        float sw = fmaxf(w0 + w1, 1e-9f);
        w0 /= sw; w1 /= sw;
        int p0 = atomicAdd(&g_cnt[i0], 1);
        int p1 = atomicAdd(&g_cnt[i1], 1);
        g_tok[i0 * Tn + p0] = t;
        g_tok[i1 * Tn + p1] = t;
        g_tk [t * 2]     = i0 * Tn + p0;  g_tkw[t * 2]     = w0;
        g_tk [t * 2 + 1] = i1 * Tn + p1;  g_tkw[t * 2 + 1] = w1;
    }
}

__global__ void aux_kernel(float* out, int aux_idx) {
    if (threadIdx.x == 0) {
        float s = 0.0f;
        #pragma unroll
        for (int e = 0; e < En; e++)
            s += ((float)g_cnt[e] / (float)Tn) * (g_imp[e] / (float)Tn);
        out[aux_idx] = (float)En * s * 0.01f;
    }
}

// transpose + split weights: src [E][K][N] fp32 -> dst [E][N][K] bf16 hi/lo
__global__ void wconv_kernel(const float* __restrict__ Wg,
                             const float* __restrict__ Wu,
                             const float* __restrict__ Wd) {
    int mi = blockIdx.z % 3, e = blockIdx.z / 3;
    const float* src = (mi == 0 ? Wg : (mi == 1 ? Wu : Wd)) + (size_t)e * 1024 * 1024;
    __nv_bfloat16* dh = (mi == 0 ? g_wg_h : (mi == 1 ? g_wu_h : g_wd_h)) + (size_t)e * 1024 * 1024;
    __nv_bfloat16* dl = (mi == 0 ? g_wg_l : (mi == 1 ? g_wu_l : g_wd_l)) + (size_t)e * 1024 * 1024;
    __shared__ float tile[32][33];
    int k0 = blockIdx.x * 32, n0 = blockIdx.y * 32;
    int tx = threadIdx.x & 31, ty = threadIdx.x >> 5;
    #pragma unroll
    for (int i = 0; i < 4; i++) {
        int k = ty + i * 8;
        tile[k][tx] = src[(size_t)(k0 + k) * 1024 + n0 + tx];
    }
    __syncthreads();
    #pragma unroll
    for (int i = 0; i < 4; i++) {
        int n = ty + i * 8;
        float v = tile[tx][n];
        __nv_bfloat16 h = __float2bfloat16(v);
        __nv_bfloat16 l = __float2bfloat16(v - __bfloat162float(h));
        size_t o = (size_t)(n0 + n) * 1024 + k0 + tx;
        dh[o] = h;  dl[o] = l;
    }
}

__global__ void combine_kernel(float* __restrict__ out) {
    int t = blockIdx.x;
    int s0 = g_tk[2 * t], s1 = g_tk[2 * t + 1];
    float w0 = g_tkw[2 * t], w1 = g_tkw[2 * t + 1];
    const float4* a = (const float4*)(g_out2 + (size_t)s0 * Hn);
    const float4* b = (const float4*)(g_out2 + (size_t)s1 * Hn);
    float4* o = (float4*)(out + (size_t)t * Hn);
    int i = threadIdx.x;
    float4 va = a[i], vb = b[i];
    o[i] = make_float4(w0 * va.x + w1 * vb.x, w0 * va.y + w1 * vb.y,
                       w0 * va.z + w1 * vb.z, w0 * va.w + w1 * vb.w);
}

// ==================== smem layout ====================
#define ROWB 80
#define A_ARR 10240          // 128 rows * 80B
#define B_ARR 5120           // 64 rows * 80B
// gemm1: A 2 bufs x 2 arrays, then B 3 bufs x 4 arrays
#define G1_ABUF (2 * A_ARR)              // 20480 per buf
#define G1_BBUF (4 * B_ARR)              // 20480 per buf
#define G1_BBASE (2 * G1_ABUF)           // 40960
#define G1_SMEM (G1_BBASE + 3 * G1_BBUF + 512)   // 102912 (+sTok)
// gemm2: unified stage = A(2 arrays) + B(2 arrays), 4 stages
#define G2_STG (2 * A_ARR + 2 * B_ARR)   // 30720
#define G2_SMEM (4 * G2_STG)             // 122880

// ==================== GEMM1 ====================
__global__ __launch_bounds__(256, 1)
void gemm1_kernel(const float* __restrict__ x) {
    extern __shared__ char smem[];
    int e = blockIdx.z;
    int n_rows = g_cnt[e];
    int mBase = blockIdx.y * 128;
    if (mBase >= n_rows) return;
    int n0 = blockIdx.x * 64;

    uint32_t sb = smem_u32(smem);
    int tid = threadIdx.x, wid = tid >> 5, lane = tid & 31;
    int* sTok = (int*)(smem + G1_BBASE + 3 * G1_BBUF);

    if (tid < 128) {
        int m = mBase + tid;
        sTok[tid] = (m < n_rows) ? g_tok[e * Tn + m] : -1;
    }
    __syncthreads();

    int wm = wid & 3, wn = wid >> 2;
    int ar = lane & 15, ac = lane >> 4;
    int brow = (lane >> 4) * 8 + (lane & 7);
    int bhalf = (lane & 15) >> 3;

    // B fill: 4 arrays (Gh,Gl,Uh,Ul), 1 cpa16 per array per thread
    int frow = tid >> 2, fch = tid & 3;
    uint32_t fdoff = (uint32_t)frow * ROWB + fch * 16;

    float4 rA[4];
    float aG[2][4][4] = {{{0}}}, aU[2][4][4] = {{{0}}};

    // prologue: B stages 0,1 + A regs stage 0
    #pragma unroll
    for (int p = 0; p < 2; p++) {
        size_t wo = ((size_t)(e * In + n0 + frow)) * Hn + p * 32 + fch * 8;
        uint32_t bb = sb + G1_BBASE + p * G1_BBUF + fdoff;
        cpa16(bb,                g_wg_h + wo);
        cpa16(bb + B_ARR,        g_wg_l + wo);
        cpa16(bb + 2 * B_ARR,    g_wu_h + wo);
        cpa16(bb + 3 * B_ARR,    g_wu_l + wo);
        CP_COMMIT();
    }
    #pragma unroll
    for (int it = 0; it < 4; it++) {
        int idx = it * 256 + tid, row = idx >> 3, c4 = idx & 7;
        int tok = sTok[row];
        rA[it] = (tok >= 0) ? *(const float4*)(x + (size_t)tok * Hn + c4 * 4)
                            : make_float4(0.f, 0.f, 0.f, 0.f);
    }

    #pragma unroll 1
    for (int s = 0; s < 32; s++) {
        // store A regs (stage s) into A buf s&1
        {
            char* Ah = smem + (s & 1) * G1_ABUF;
            char* Al = Ah + A_ARR;
            #pragma unroll
            for (int it = 0; it < 4; it++) {
                int idx = it * 256 + tid, row = idx >> 3, c4 = idx & 7;
                uint32_t h0, l0, h1, l1;
                split2(rA[it].x, rA[it].y, h0, l0);
                split2(rA[it].z, rA[it].w, h1, l1);
                uint32_t off = row * ROWB + c4 * 8;
                *(uint2*)(Ah + off) = make_uint2(h0, h1);
                *(uint2*)(Al + off) = make_uint2(l0, l1);
            }
        }
        // issue B for stage s+2
        if (s + 2 < 32) {
            size_t wo = ((size_t)(e * In + n0 + frow)) * Hn + (s + 2) * 32 + fch * 8;
            uint32_t bb = sb + G1_BBASE + ((s + 2) % 3) * G1_BBUF + fdoff;
            cpa16(bb,             g_wg_h + wo);
            cpa16(bb + B_ARR,     g_wg_l + wo);
            cpa16(bb + 2 * B_ARR, g_wu_h + wo);
            cpa16(bb + 3 * B_ARR, g_wu_l + wo);
        }
        CP_COMMIT();
        CP_WAIT2();
        __syncthreads();

        // prefetch A regs for stage s+1 (latency hidden under compute)
        if (s < 31) {
            int k0 = (s + 1) * 32;
            #pragma unroll
            for (int it = 0; it < 4; it++) {
                int idx = it * 256 + tid, row = idx >> 3, c4 = idx & 7;
                int tok = sTok[row];
                rA[it] = (tok >= 0) ? *(const float4*)(x + (size_t)tok * Hn + k0 + c4 * 4)
                                    : make_float4(0.f, 0.f, 0.f, 0.f);
            }
        }

        // compute stage s
        uint32_t aBase = sb + (s & 1) * G1_ABUF;
        uint32_t gBase = sb + G1_BBASE + (s % 3) * G1_BBUF;
        #pragma unroll
        for (int kk = 0; kk < 2; kk++) {
            int kb = kk * 32;
            uint32_t ah[2][4], al[2][4];
            #pragma unroll
            for (int mt = 0; mt < 2; mt++) {
                uint32_t ad = aBase + (uint32_t)(wm * 32 + mt * 16 + ar) * ROWB + kb + ac * 16;
                LDM4(ah[mt], ad);
                LDM4(al[mt], ad + A_ARR);
            }
            uint32_t bgh[2][4], bgl[2][4], buh[2][4], bul[2][4];
            #pragma unroll
            for (int ng = 0; ng < 2; ng++) {
                uint32_t bd = gBase + (uint32_t)(wn * 32 + ng * 16 + brow) * ROWB + kb + bhalf * 16;
                LDM4(bgh[ng], bd);
                LDM4(bgl[ng], bd + B_ARR);
                LDM4(buh[ng], bd + 2 * B_ARR);
                LDM4(bul[ng], bd + 3 * B_ARR);
            }
            #pragma unroll
            for (int mt = 0; mt < 2; mt++)
                #pragma unroll
                for (int nt = 0; nt < 4; nt++) {
                    int ng = nt >> 1, p = (nt & 1) * 2;
                    MMA(aG[mt][nt], ah[mt], bgh[ng][p], bgh[ng][p + 1]);
                    MMA(aU[mt][nt], ah[mt], buh[ng][p], buh[ng][p + 1]);
                }
            #pragma unroll
            for (int mt = 0; mt < 2; mt++)
                #pragma unroll
                for (int nt = 0; nt < 4; nt++) {
                    int ng = nt >> 1, p = (nt & 1) * 2;
                    MMA(aG[mt][nt], ah[mt], bgl[ng][p], bgl[ng][p + 1]);
                    MMA(aU[mt][nt], ah[mt], bul[ng][p], bul[ng][p + 1]);
                }
            #pragma unroll
            for (int mt = 0; mt < 2; mt++)
                #pragma unroll
                for (int nt = 0; nt < 4; nt++) {
                    int ng = nt >> 1, p = (nt & 1) * 2;
                    MMA(aG[mt][nt], al[mt], bgh[ng][p], bgh[ng][p + 1]);
                    MMA(aU[mt][nt], al[mt], buh[ng][p], buh[ng][p + 1]);
                }
        }
        __syncthreads();
    }

    // epilogue: silu(g)*u -> split bf16 intermediate
    #pragma unroll
    for (int mt = 0; mt < 2; mt++) {
        #pragma unroll
        for (int nt = 0; nt < 4; nt++) {
            int c = n0 + wn * 32 + nt * 8 + (lane & 3) * 2;
            #pragma unroll
            for (int h = 0; h < 2; h++) {
                int r = mBase + wm * 32 + mt * 16 + (lane >> 2) + h * 8;
                if (r < n_rows) {
                    float g0 = aG[mt][nt][h * 2],     u0 = aU[mt][nt][h * 2];
                    float g1 = aG[mt][nt][h * 2 + 1], u1 = aU[mt][nt][h * 2 + 1];
                    float i0 = u0 * g0 / (1.0f + __expf(-g0));
                    float i1 = u1 * g1 / (1.0f + __expf(-g1));
                    uint32_t ph, pl;
                    split2(i0, i1, ph, pl);
                    size_t o = ((size_t)e * Tn + r) * In + c;
                    *(uint32_t*)(g_ih + o) = ph;
                    *(uint32_t*)(g_il + o) = pl;
                }
            }
        }
    }
}

// ==================== GEMM2: all-cp.async, 4 stages ====================
__device__ __forceinline__ void g2_fill(uint32_t sb, int buf, int k0,
                                        int e, int mBase, int n0, int tid) {
    uint32_t st = sb + buf * G2_STG;
    #pragma unroll
    for (int it = 0; it < 2; it++) {
        int idx = it * 256 + tid;
        int row = idx >> 2, ch = idx & 3;
        size_t ao = ((size_t)(e * Tn + mBase + row)) * In + k0 + ch * 8;
        uint32_t doff = (uint32_t)row * ROWB + ch * 16;
        cpa16(st + doff,         g_ih + ao);
        cpa16(st + A_ARR + doff, g_il + ao);
    }
    int row = tid >> 2, ch = tid & 3;
    size_t wo = ((size_t)(e * Hn + n0 + row)) * In + k0 + ch * 8;
    uint32_t doff = (uint32_t)row * ROWB + ch * 16;
    cpa16(st + 2 * A_ARR + doff,         g_wd_h + wo);
    cpa16(st + 2 * A_ARR + B_ARR + doff, g_wd_l + wo);
}

__global__ __launch_bounds__(256, 1)
void gemm2_kernel() {
    extern __shared__ char smem[];
    int e = blockIdx.z;
    int n_rows = g_cnt[e];
    int mBase = blockIdx.y * 128;
    if (mBase >= n_rows) return;
    int n0 = blockIdx.x * 64;

    uint32_t sb = smem_u32(smem);
    int tid = threadIdx.x, wid = tid >> 5, lane = tid & 31;
    int wm = wid & 3, wn = wid >> 2;
    int ar = lane & 15, ac = lane >> 4;
    int brow = (lane >> 4) * 8 + (lane & 7);
    int bhalf = (lane & 15) >> 3;

    float acc[2][4][4] = {{{0}}};

    #pragma unroll
    for (int p = 0; p < 3; p++) {
        g2_fill(sb, p, p * 32, e, mBase, n0, tid);
        CP_COMMIT();
    }

    #pragma unroll 1
    for (int s = 0; s < 32; s++) {
        if (s + 3 < 32) g2_fill(sb, (s + 3) & 3, (s + 3) * 32, e, mBase, n0, tid);
        CP_COMMIT();
        CP_WAIT3();
        __syncthreads();

        uint32_t aBase = sb + (s & 3) * G2_STG;
        uint32_t bBase = aBase + 2 * A_ARR;
        #pragma unroll
        for (int kk = 0; kk < 2; kk++) {
            int kb = kk * 32;
            uint32_t ah[2][4], al[2][4];
            #pragma unroll
            for (int mt = 0; mt < 2; mt++) {
                uint32_t ad = aBase + (uint32_t)(wm * 32 + mt * 16 + ar) * ROWB + kb + ac * 16;
                LDM4(ah[mt], ad);
                LDM4(al[mt], ad + A_ARR);
            }
            uint32_t bh[2][4], bl[2][4];
            #pragma unroll
            for (int ng = 0; ng < 2; ng++) {
                uint32_t bd = bBase + (uint32_t)(wn * 32 + ng * 16 + brow) * ROWB + kb + bhalf * 16;
                LDM4(bh[ng], bd);
                LDM4(bl[ng], bd + B_ARR);
            }
            #pragma unroll
            for (int mt = 0; mt < 2; mt++)
                #pragma unroll
                for (int nt = 0; nt < 4; nt++) {
                    int ng = nt >> 1, p = (nt & 1) * 2;
                    MMA(acc[mt][nt], ah[mt], bh[ng][p], bh[ng][p + 1]);
                }
            #pragma unroll
            for (int mt = 0; mt < 2; mt++)
                #pragma unroll
                for (int nt = 0; nt < 4; nt++) {
                    int ng = nt >> 1, p = (nt & 1) * 2;
                    MMA(acc[mt][nt], ah[mt], bl[ng][p], bl[ng][p + 1]);
                }
            #pragma unroll
            for (int mt = 0; mt < 2; mt++)
                #pragma unroll
                for (int nt = 0; nt < 4; nt++) {
                    int ng = nt >> 1, p = (nt & 1) * 2;
                    MMA(acc[mt][nt], al[mt], bh[ng][p], bh[ng][p + 1]);
                }
        }
        __syncthreads();
    }

    #pragma unroll
    for (int mt = 0; mt < 2; mt++) {
        #pragma unroll
        for (int nt = 0; nt < 4; nt++) {
            int c = n0 + wn * 32 + nt * 8 + (lane & 3) * 2;
            #pragma unroll
            for (int h = 0; h < 2; h++) {
                int r = mBase + wm * 32 + mt * 16 + (lane >> 2) + h * 8;
                if (r < n_rows)
                    *(float2*)(g_out2 + ((size_t)e * Tn + r) * Hn + c) =
                        make_float2(acc[mt][nt][h * 2], acc[mt][nt][h * 2 + 1]);
            }
        }
    }
}

// ==================== launch ====================
extern "C" void kernel_launch(void* const* d_in, const int* in_sizes, int n_in,
                              void* d_out, int out_size) {
    const float* x  = (const float*)d_in[0];
    const float* Wr = (const float*)d_in[1];
    const float* Wg = (const float*)d_in[2];
    const float* Wu = (const float*)d_in[3];
    const float* Wd = (const float*)d_in[4];
    float* out = (float*)d_out;

    cudaFuncSetAttribute(gemm1_kernel, cudaFuncAttributeMaxDynamicSharedMemorySize, G1_SMEM);
    cudaFuncSetAttribute(gemm2_kernel, cudaFuncAttributeMaxDynamicSharedMemorySize, G2_SMEM);

    init_kernel<<<1, 32>>>();

    dim3 wcg(32, 32, 3 * En);
    wconv_kernel<<<wcg, 256>>>(Wg, Wu, Wd);

    router_kernel<<<Tn, 256>>>(x, Wr);
    if (out_size > Tn * Hn)
        aux_kernel<<<1, 32>>>(out, Tn * Hn);

    dim3 g1(In / 64, Tn / 128, En);
    gemm1_kernel<<<g1, 256, G1_SMEM>>>(x);

    dim3 g2(Hn / 64, Tn / 128, En);
    gemm2_kernel<<<g2, 256, G2_SMEM>>>();

    combine_kernel<<<Tn, 256>>>(out);
}

// round 6
// speedup vs baseline: 1.0810x; 1.0551x over previous
#include <cuda_runtime.h>
#include <cuda_bf16.h>
#include <stdint.h>
#include <math.h>

#define Tn 4096
#define Hn 1024
#define En 8
#define In 1024

// ==================== scratch ====================
__device__ int   g_cnt[En];
__device__ float g_imp[En];
__device__ int   g_tok[En * Tn];
__device__ int   g_tk [Tn * 2];
__device__ float g_tkw[Tn * 2];
// split intermediate (bf16 hi/lo), written by gemm1 epilogue
__device__ __nv_bfloat16 g_ih[(size_t)En * Tn * In], g_il[(size_t)En * Tn * In];
// per-slot expert output
__device__ float g_out2[(size_t)En * Tn * Hn];

// ==================== helpers ====================
__device__ __forceinline__ uint32_t smem_u32(const void* p) {
    uint32_t a;
    asm("{ .reg .u64 t; cvta.to.shared.u64 t, %1; cvt.u32.u64 %0, t; }" : "=r"(a) : "l"(p));
    return a;
}

#define LDM4(r, addr)                                                          \
    asm volatile("ldmatrix.sync.aligned.m8n8.x4.shared.b16 {%0,%1,%2,%3}, [%4];" \
        : "=r"((r)[0]), "=r"((r)[1]), "=r"((r)[2]), "=r"((r)[3]) : "r"(addr))

#define MMA(d, a, b0, b1)                                                      \
    asm volatile("mma.sync.aligned.m16n8k16.row.col.f32.bf16.bf16.f32 "        \
        "{%0,%1,%2,%3}, {%4,%5,%6,%7}, {%8,%9}, {%0,%1,%2,%3};"                \
        : "+f"((d)[0]), "+f"((d)[1]), "+f"((d)[2]), "+f"((d)[3])               \
        : "r"((a)[0]), "r"((a)[1]), "r"((a)[2]), "r"((a)[3]), "r"(b0), "r"(b1))

__device__ __forceinline__ void split2(float a, float b, uint32_t& hi, uint32_t& lo) {
    __nv_bfloat16 ha = __float2bfloat16(a), hb = __float2bfloat16(b);
    float ra = a - __bfloat162float(ha);
    float rb = b - __bfloat162float(hb);
    __nv_bfloat162 H; H.x = ha; H.y = hb;
    __nv_bfloat162 L = __floats2bfloat162_rn(ra, rb);
    hi = *(uint32_t*)&H;  lo = *(uint32_t*)&L;
}

// ==================== small kernels ====================
__global__ void init_kernel() {
    if (threadIdx.x < En) { g_cnt[threadIdx.x] = 0; g_imp[threadIdx.x] = 0.0f; }
}

__global__ void router_kernel(const float* __restrict__ x, const float* __restrict__ Wr) {
    int t = blockIdx.x;
    int warp = threadIdx.x >> 5, lane = threadIdx.x & 31;
    const float* xt = x + (size_t)t * Hn;
    float acc = 0.0f;
    for (int h = lane; h < Hn; h += 32) acc += xt[h] * Wr[h * En + warp];
    #pragma unroll
    for (int o = 16; o > 0; o >>= 1) acc += __shfl_xor_sync(0xffffffff, acc, o);
    __shared__ float logits[En];
    if (lane == 0) logits[warp] = acc;
    __syncthreads();
    if (threadIdx.x == 0) {
        float mx = logits[0];
        #pragma unroll
        for (int e = 1; e < En; e++) mx = fmaxf(mx, logits[e]);
        float p[En], s = 0.0f;
        #pragma unroll
        for (int e = 0; e < En; e++) { p[e] = expf(logits[e] - mx); s += p[e]; }
        float inv = 1.0f / s;
        #pragma unroll
        for (int e = 0; e < En; e++) { p[e] *= inv; atomicAdd(&g_imp[e], p[e]); }
        int i0 = 0;
        #pragma unroll
        for (int e = 1; e < En; e++) if (p[e] > p[i0]) i0 = e;
        int i1 = (i0 == 0) ? 1 : 0;
        #pragma unroll
        for (int e = 0; e < En; e++) if (e != i0 && p[e] > p[i1]) i1 = e;
        float w0 = p[i0], w1 = p[i1];
        float sw = fmaxf(w0 + w1, 1e-9f);
        w0 /= sw; w1 /= sw;
        int p0 = atomicAdd(&g_cnt[i0], 1);
        int p1 = atomicAdd(&g_cnt[i1], 1);
        g_tok[i0 * Tn + p0] = t;
        g_tok[i1 * Tn + p1] = t;
        g_tk [t * 2]     = i0 * Tn + p0;  g_tkw[t * 2]     = w0;
        g_tk [t * 2 + 1] = i1 * Tn + p1;  g_tkw[t * 2 + 1] = w1;
    }
}

__global__ void aux_kernel(float* out, int aux_idx) {
    if (threadIdx.x == 0) {
        float s = 0.0f;
        #pragma unroll
        for (int e = 0; e < En; e++)
            s += ((float)g_cnt[e] / (float)Tn) * (g_imp[e] / (float)Tn);
        out[aux_idx] = (float)En * s * 0.01f;
    }
}

__global__ void combine_kernel(float* __restrict__ out) {
    int t = blockIdx.x;
    int s0 = g_tk[2 * t], s1 = g_tk[2 * t + 1];
    float w0 = g_tkw[2 * t], w1 = g_tkw[2 * t + 1];
    const float4* a = (const float4*)(g_out2 + (size_t)s0 * Hn);
    const float4* b = (const float4*)(g_out2 + (size_t)s1 * Hn);
    float4* o = (float4*)(out + (size_t)t * Hn);
    int i = threadIdx.x;
    float4 va = a[i], vb = b[i];
    o[i] = make_float4(w0 * va.x + w1 * vb.x, w0 * va.y + w1 * vb.y,
                       w0 * va.z + w1 * vb.z, w0 * va.w + w1 * vb.w);
}

// ==================== smem layout ====================
#define ROWB 80
#define A_ARR 10240            // 128 rows * 80B
#define B_ARR 5120             // 64 rows * 80B
#define G1_STG (2 * A_ARR + 4 * B_ARR)   // 40960
#define G1_SMEM (2 * G1_STG + 512)
#define G2_STG (2 * A_ARR + 2 * B_ARR)   // 30720
#define G2_SMEM (2 * G2_STG)

// warp layout: 16 warps as 4(M) x 4(N); warp tile 32M x 16N
// ==================== GEMM1 ====================
__global__ __launch_bounds__(512, 1)
void gemm1_kernel(const float* __restrict__ x,
                  const float* __restrict__ Wg,
                  const float* __restrict__ Wu) {
    extern __shared__ char smem[];
    int e = blockIdx.z;
    int n_rows = g_cnt[e];
    int mBase = blockIdx.y * 128;
    if (mBase >= n_rows) return;
    int n0 = blockIdx.x * 64;

    uint32_t sb = smem_u32(smem);
    int tid = threadIdx.x, wid = tid >> 5, lane = tid & 31;
    int* sTok = (int*)(smem + 2 * G1_STG);

    if (tid < 128) {
        int m = mBase + tid;
        sTok[tid] = (m < n_rows) ? g_tok[e * Tn + m] : -1;
    }
    __syncthreads();

    const float* Wg_e = Wg + (size_t)e * Hn * In + n0;
    const float* Wu_e = Wu + (size_t)e * Hn * In + n0;

    int wm = wid & 3, wn = wid >> 2;
    int ar = lane & 15, ac = lane >> 4;
    int brow = (lane >> 4) * 8 + (lane & 7);
    int bhalf = (lane & 15) >> 3;

    // fill assignments
    int bn  = tid & 63;        // B: n within tile
    int bkq = tid >> 6;        // B: k-quarter (0..7), 4 k's each

    float4 rA[2];
    float rG[4], rU[4];

    // prologue: prefetch stage 0
    #pragma unroll
    for (int it = 0; it < 2; it++) {
        int idx = it * 512 + tid, row = idx >> 3, c4 = idx & 7;
        int tok = sTok[row];
        rA[it] = (tok >= 0) ? *(const float4*)(x + (size_t)tok * Hn + c4 * 4)
                            : make_float4(0.f, 0.f, 0.f, 0.f);
    }
    #pragma unroll
    for (int j = 0; j < 4; j++) {
        size_t o = (size_t)(bkq * 4 + j) * In + bn;
        rG[j] = Wg_e[o];  rU[j] = Wu_e[o];
    }

    float aG[2][2][4] = {{{0}}}, aU[2][2][4] = {{{0}}};

    #pragma unroll 1
    for (int s = 0; s < 32; s++) {
        int cur = s & 1;
        char* st = smem + cur * G1_STG;

        // store prefetched regs
        {
            char* Ah = st;  char* Al = st + A_ARR;
            #pragma unroll
            for (int it = 0; it < 2; it++) {
                int idx = it * 512 + tid, row = idx >> 3, c4 = idx & 7;
                uint32_t h0, l0, h1, l1;
                split2(rA[it].x, rA[it].y, h0, l0);
                split2(rA[it].z, rA[it].w, h1, l1);
                uint32_t off = row * ROWB + c4 * 8;
                *(uint2*)(Ah + off) = make_uint2(h0, h1);
                *(uint2*)(Al + off) = make_uint2(l0, l1);
            }
            char* Gh = st + 2 * A_ARR;
            uint32_t gh[2], gl[2], uh[2], ul[2];
            split2(rG[0], rG[1], gh[0], gl[0]);
            split2(rG[2], rG[3], gh[1], gl[1]);
            split2(rU[0], rU[1], uh[0], ul[0]);
            split2(rU[2], rU[3], uh[1], ul[1]);
            uint32_t boff = bn * ROWB + bkq * 8;
            *(uint2*)(Gh + boff)             = make_uint2(gh[0], gh[1]);
            *(uint2*)(Gh + B_ARR + boff)     = make_uint2(gl[0], gl[1]);
            *(uint2*)(Gh + 2 * B_ARR + boff) = make_uint2(uh[0], uh[1]);
            *(uint2*)(Gh + 3 * B_ARR + boff) = make_uint2(ul[0], ul[1]);
        }
        __syncthreads();

        // prefetch next stage
        if (s < 31) {
            int k0 = (s + 1) * 32;
            #pragma unroll
            for (int it = 0; it < 2; it++) {
                int idx = it * 512 + tid, row = idx >> 3, c4 = idx & 7;
                int tok = sTok[row];
                rA[it] = (tok >= 0) ? *(const float4*)(x + (size_t)tok * Hn + k0 + c4 * 4)
                                    : make_float4(0.f, 0.f, 0.f, 0.f);
            }
            #pragma unroll
            for (int j = 0; j < 4; j++) {
                size_t o = (size_t)(k0 + bkq * 4 + j) * In + bn;
                rG[j] = Wg_e[o];  rU[j] = Wu_e[o];
            }
        }

        // compute current stage
        uint32_t aBase = sb + cur * G1_STG;
        uint32_t gBase = aBase + 2 * A_ARR;
        #pragma unroll
        for (int kk = 0; kk < 2; kk++) {
            int kb = kk * 32;
            uint32_t ah[2][4], al[2][4];
            #pragma unroll
            for (int mt = 0; mt < 2; mt++) {
                uint32_t ad = aBase + (uint32_t)(wm * 32 + mt * 16 + ar) * ROWB + kb + ac * 16;
                LDM4(ah[mt], ad);
                LDM4(al[mt], ad + A_ARR);
            }
            uint32_t bgh[4], bgl[4], buh[4], bul[4];
            {
                uint32_t bd = gBase + (uint32_t)(wn * 16 + brow) * ROWB + kb + bhalf * 16;
                LDM4(bgh, bd);
                LDM4(bgl, bd + B_ARR);
                LDM4(buh, bd + 2 * B_ARR);
                LDM4(bul, bd + 3 * B_ARR);
            }
            #pragma unroll
            for (int mt = 0; mt < 2; mt++)
                #pragma unroll
                for (int nt = 0; nt < 2; nt++) {
                    int p = nt * 2;
                    MMA(aG[mt][nt], ah[mt], bgh[p], bgh[p + 1]);
                    MMA(aU[mt][nt], ah[mt], buh[p], buh[p + 1]);
                }
            #pragma unroll
            for (int mt = 0; mt < 2; mt++)
                #pragma unroll
                for (int nt = 0; nt < 2; nt++) {
                    int p = nt * 2;
                    MMA(aG[mt][nt], ah[mt], bgl[p], bgl[p + 1]);
                    MMA(aU[mt][nt], ah[mt], bul[p], bul[p + 1]);
                }
            #pragma unroll
            for (int mt = 0; mt < 2; mt++)
                #pragma unroll
                for (int nt = 0; nt < 2; nt++) {
                    int p = nt * 2;
                    MMA(aG[mt][nt], al[mt], bgh[p], bgh[p + 1]);
                    MMA(aU[mt][nt], al[mt], buh[p], buh[p + 1]);
                }
        }
        __syncthreads();
    }

    // epilogue: silu(g)*u -> split bf16 intermediate
    #pragma unroll
    for (int mt = 0; mt < 2; mt++) {
        #pragma unroll
        for (int nt = 0; nt < 2; nt++) {
            int c = n0 + wn * 16 + nt * 8 + (lane & 3) * 2;
            #pragma unroll
            for (int h = 0; h < 2; h++) {
                int r = mBase + wm * 32 + mt * 16 + (lane >> 2) + h * 8;
                if (r < n_rows) {
                    float g0 = aG[mt][nt][h * 2],     u0 = aU[mt][nt][h * 2];
                    float g1 = aG[mt][nt][h * 2 + 1], u1 = aU[mt][nt][h * 2 + 1];
                    float i0 = u0 * g0 / (1.0f + __expf(-g0));
                    float i1 = u1 * g1 / (1.0f + __expf(-g1));
                    uint32_t ph, pl;
                    split2(i0, i1, ph, pl);
                    size_t o = ((size_t)e * Tn + r) * In + c;
                    *(uint32_t*)(g_ih + o) = ph;
                    *(uint32_t*)(g_il + o) = pl;
                }
            }
        }
    }
}

// ==================== GEMM2 ====================
__global__ __launch_bounds__(512, 1)
void gemm2_kernel(const float* __restrict__ Wd) {
    extern __shared__ char smem[];
    int e = blockIdx.z;
    int n_rows = g_cnt[e];
    int mBase = blockIdx.y * 128;
    if (mBase >= n_rows) return;
    int n0 = blockIdx.x * 64;

    uint32_t sb = smem_u32(smem);
    int tid = threadIdx.x, wid = tid >> 5, lane = tid & 31;
    int wm = wid & 3, wn = wid >> 2;
    int ar = lane & 15, ac = lane >> 4;
    int brow = (lane >> 4) * 8 + (lane & 7);
    int bhalf = (lane & 15) >> 3;

    const __nv_bfloat16* Ah_g = g_ih + ((size_t)(e * Tn + mBase)) * In;
    const __nv_bfloat16* Al_g = g_il + ((size_t)(e * Tn + mBase)) * In;
    const float* Bw = Wd + (size_t)e * In * Hn + n0;

    int bn  = tid & 63;
    int bkq = tid >> 6;
    // A fill: 128 rows x 4 chunks of 8 bf16; 512 threads -> 1 chunk each
    int arow = tid >> 2, ach = tid & 3;

    uint4 rAh, rAl;
    float rB[4];

    rAh = *(const uint4*)(Ah_g + (size_t)arow * In + ach * 8);
    rAl = *(const uint4*)(Al_g + (size_t)arow * In + ach * 8);
    #pragma unroll
    for (int j = 0; j < 4; j++)
        rB[j] = Bw[(size_t)(bkq * 4 + j) * Hn + bn];

    float acc[2][2][4] = {{{0}}};

    #pragma unroll 1
    for (int s = 0; s < 32; s++) {
        int cur = s & 1;
        char* st = smem + cur * G2_STG;
        {
            uint32_t off = arow * ROWB + ach * 16;
            *(uint4*)(st + off)         = rAh;
            *(uint4*)(st + A_ARR + off) = rAl;
            char* Bh = st + 2 * A_ARR;
            uint32_t bh[2], bl[2];
            split2(rB[0], rB[1], bh[0], bl[0]);
            split2(rB[2], rB[3], bh[1], bl[1]);
            uint32_t boff = bn * ROWB + bkq * 8;
            *(uint2*)(Bh + boff)         = make_uint2(bh[0], bh[1]);
            *(uint2*)(Bh + B_ARR + boff) = make_uint2(bl[0], bl[1]);
        }
        __syncthreads();

        if (s < 31) {
            int k0 = (s + 1) * 32;
            rAh = *(const uint4*)(Ah_g + (size_t)arow * In + k0 + ach * 8);
            rAl = *(const uint4*)(Al_g + (size_t)arow * In + k0 + ach * 8);
            #pragma unroll
            for (int j = 0; j < 4; j++)
                rB[j] = Bw[(size_t)(k0 + bkq * 4 + j) * Hn + bn];
        }

        uint32_t aBase = sb + cur * G2_STG;
        uint32_t bBase = aBase + 2 * A_ARR;
        #pragma unroll
        for (int kk = 0; kk < 2; kk++) {
            int kb = kk * 32;
            uint32_t ah[2][4], al[2][4];
            #pragma unroll
            for (int mt = 0; mt < 2; mt++) {
                uint32_t ad = aBase + (uint32_t)(wm * 32 + mt * 16 + ar) * ROWB + kb + ac * 16;
                LDM4(ah[mt], ad);
                LDM4(al[mt], ad + A_ARR);
            }
            uint32_t bh[4], bl[4];
            {
                uint32_t bd = bBase + (uint32_t)(wn * 16 + brow) * ROWB + kb + bhalf * 16;
                LDM4(bh, bd);
                LDM4(bl, bd + B_ARR);
            }
            #pragma unroll
            for (int mt = 0; mt < 2; mt++)
                #pragma unroll
                for (int nt = 0; nt < 2; nt++) {
                    int p = nt * 2;
                    MMA(acc[mt][nt], ah[mt], bh[p], bh[p + 1]);
                }
            #pragma unroll
            for (int mt = 0; mt < 2; mt++)
                #pragma unroll
                for (int nt = 0; nt < 2; nt++) {
                    int p = nt * 2;
                    MMA(acc[mt][nt], ah[mt], bl[p], bl[p + 1]);
                }
            #pragma unroll
            for (int mt = 0; mt < 2; mt++)
                #pragma unroll
                for (int nt = 0; nt < 2; nt++) {
                    int p = nt * 2;
                    MMA(acc[mt][nt], al[mt], bh[p], bh[p + 1]);
                }
        }
        __syncthreads();
    }

    #pragma unroll
    for (int mt = 0; mt < 2; mt++) {
        #pragma unroll
        for (int nt = 0; nt < 2; nt++) {
            int c = n0 + wn * 16 + nt * 8 + (lane & 3) * 2;
            #pragma unroll
            for (int h = 0; h < 2; h++) {
                int r = mBase + wm * 32 + mt * 16 + (lane >> 2) + h * 8;
                if (r < n_rows)
                    *(float2*)(g_out2 + ((size_t)e * Tn + r) * Hn + c) =
                        make_float2(acc[mt][nt][h * 2], acc[mt][nt][h * 2 + 1]);
            }
        }
    }
}

// ==================== launch ====================
extern "C" void kernel_launch(void* const* d_in, const int* in_sizes, int n_in,
                              void* d_out, int out_size) {
    const float* x  = (const float*)d_in[0];
    const float* Wr = (const float*)d_in[1];
    const float* Wg = (const float*)d_in[2];
    const float* Wu = (const float*)d_in[3];
    const float* Wd = (const float*)d_in[4];
    float* out = (float*)d_out;

    cudaFuncSetAttribute(gemm1_kernel, cudaFuncAttributeMaxDynamicSharedMemorySize, G1_SMEM);
    cudaFuncSetAttribute(gemm2_kernel, cudaFuncAttributeMaxDynamicSharedMemorySize, G2_SMEM);

    init_kernel<<<1, 32>>>();
    router_kernel<<<Tn, 256>>>(x, Wr);
    if (out_size > Tn * Hn)
        aux_kernel<<<1, 32>>>(out, Tn * Hn);

    dim3 g1(In / 64, Tn / 128, En);
    gemm1_kernel<<<g1, 512, G1_SMEM>>>(x, Wg, Wu);

    dim3 g2(Hn / 64, Tn / 128, En);
    gemm2_kernel<<<g2, 512, G2_SMEM>>>(Wd);

    combine_kernel<<<Tn, 256>>>(out);
}

// round 7
// speedup vs baseline: 1.1546x; 1.0681x over previous
#include <cuda_runtime.h>
#include <cuda_bf16.h>
#include <stdint.h>
#include <math.h>

#define Tn 4096
#define Hn 1024
#define En 8
#define In 1024

// ==================== scratch ====================
__device__ int   g_cnt[En];
__device__ float g_imp[En];
__device__ int   g_tok[En * Tn];
__device__ int   g_tk [Tn * 2];
__device__ float g_tkw[Tn * 2];
__device__ __nv_bfloat16 g_ih[(size_t)En * Tn * In], g_il[(size_t)En * Tn * In];
__device__ float g_out2[(size_t)En * Tn * Hn];

// ==================== helpers ====================
__device__ __forceinline__ uint32_t smem_u32(const void* p) {
    uint32_t a;
    asm("{ .reg .u64 t; cvta.to.shared.u64 t, %1; cvt.u32.u64 %0, t; }" : "=r"(a) : "l"(p));
    return a;
}

#define LDM4(r, addr)                                                          \
    asm volatile("ldmatrix.sync.aligned.m8n8.x4.shared.b16 {%0,%1,%2,%3}, [%4];" \
        : "=r"((r)[0]), "=r"((r)[1]), "=r"((r)[2]), "=r"((r)[3]) : "r"(addr))

#define MMA(d, a, b0, b1)                                                      \
    asm volatile("mma.sync.aligned.m16n8k16.row.col.f32.bf16.bf16.f32 "        \
        "{%0,%1,%2,%3}, {%4,%5,%6,%7}, {%8,%9}, {%0,%1,%2,%3};"                \
        : "+f"((d)[0]), "+f"((d)[1]), "+f"((d)[2]), "+f"((d)[3])               \
        : "r"((a)[0]), "r"((a)[1]), "r"((a)[2]), "r"((a)[3]), "r"(b0), "r"(b1))

__device__ __forceinline__ void split2(float a, float b, uint32_t& hi, uint32_t& lo) {
    __nv_bfloat16 ha = __float2bfloat16(a), hb = __float2bfloat16(b);
    float ra = a - __bfloat162float(ha);
    float rb = b - __bfloat162float(hb);
    __nv_bfloat162 H; H.x = ha; H.y = hb;
    __nv_bfloat162 L = __floats2bfloat162_rn(ra, rb);
    hi = *(uint32_t*)&H;  lo = *(uint32_t*)&L;
}

// ==================== small kernels ====================
__global__ void init_kernel() {
    if (threadIdx.x < En) { g_cnt[threadIdx.x] = 0; g_imp[threadIdx.x] = 0.0f; }
}

__global__ void router_kernel(const float* __restrict__ x, const float* __restrict__ Wr) {
    int t = blockIdx.x;
    int warp = threadIdx.x >> 5, lane = threadIdx.x & 31;
    const float* xt = x + (size_t)t * Hn;
    float acc = 0.0f;
    for (int h = lane; h < Hn; h += 32) acc += xt[h] * Wr[h * En + warp];
    #pragma unroll
    for (int o = 16; o > 0; o >>= 1) acc += __shfl_xor_sync(0xffffffff, acc, o);
    __shared__ float logits[En];
    if (lane == 0) logits[warp] = acc;
    __syncthreads();
    if (threadIdx.x == 0) {
        float mx = logits[0];
        #pragma unroll
        for (int e = 1; e < En; e++) mx = fmaxf(mx, logits[e]);
        float p[En], s = 0.0f;
        #pragma unroll
        for (int e = 0; e < En; e++) { p[e] = expf(logits[e] - mx); s += p[e]; }
        float inv = 1.0f / s;
        #pragma unroll
        for (int e = 0; e < En; e++) { p[e] *= inv; atomicAdd(&g_imp[e], p[e]); }
        int i0 = 0;
        #pragma unroll
        for (int e = 1; e < En; e++) if (p[e] > p[i0]) i0 = e;
        int i1 = (i0 == 0) ? 1 : 0;
        #pragma unroll
        for (int e = 0; e < En; e++) if (e != i0 && p[e] > p[i1]) i1 = e;
        float w0 = p[i0], w1 = p[i1];
        float sw = fmaxf(w0 + w1, 1e-9f);
        w0 /= sw; w1 /= sw;
        int p0 = atomicAdd(&g_cnt[i0], 1);
        int p1 = atomicAdd(&g_cnt[i1], 1);
        g_tok[i0 * Tn + p0] = t;
        g_tok[i1 * Tn + p1] = t;
        g_tk [t * 2]     = i0 * Tn + p0;  g_tkw[t * 2]     = w0;
        g_tk [t * 2 + 1] = i1 * Tn + p1;  g_tkw[t * 2 + 1] = w1;
    }
}

__global__ void aux_kernel(float* out, int aux_idx) {
    if (threadIdx.x == 0) {
        float s = 0.0f;
        #pragma unroll
        for (int e = 0; e < En; e++)
            s += ((float)g_cnt[e] / (float)Tn) * (g_imp[e] / (float)Tn);
        out[aux_idx] = (float)En * s * 0.01f;
    }
}

__global__ void combine_kernel(float* __restrict__ out) {
    int t = blockIdx.x;
    int s0 = g_tk[2 * t], s1 = g_tk[2 * t + 1];
    float w0 = g_tkw[2 * t], w1 = g_tkw[2 * t + 1];
    const float4* a = (const float4*)(g_out2 + (size_t)s0 * Hn);
    const float4* b = (const float4*)(g_out2 + (size_t)s1 * Hn);
    float4* o = (float4*)(out + (size_t)t * Hn);
    int i = threadIdx.x;
    float4 va = a[i], vb = b[i];
    o[i] = make_float4(w0 * va.x + w1 * vb.x, w0 * va.y + w1 * vb.y,
                       w0 * va.z + w1 * vb.z, w0 * va.w + w1 * vb.w);
}

// ==================== smem layout ====================
#define ROWB 80
#define A_ARR 10240             // 128 rows * 80B
#define B_ARR 5120              // 64 rows * 80B
#define B2_ARR 10240            // 128 rows * 80B (gemm2 B)
#define G1_STG (2 * A_ARR + 4 * B_ARR)   // 40960
#define G1_SMEM (2 * G1_STG + 512)
#define G2_STG (2 * A_ARR + 2 * B2_ARR)  // 40960
#define G2_SMEM (2 * G2_STG)

// ==================== GEMM1: CTA 128x64(G)+64(U), 16 warps 4x4, warp 32x16 ====================
__global__ __launch_bounds__(512, 1)
void gemm1_kernel(const float* __restrict__ x,
                  const float* __restrict__ Wg,
                  const float* __restrict__ Wu) {
    extern __shared__ char smem[];
    int e = blockIdx.z;
    int n_rows = g_cnt[e];
    int mBase = blockIdx.y * 128;
    if (mBase >= n_rows) return;
    int n0 = blockIdx.x * 64;

    uint32_t sb = smem_u32(smem);
    int tid = threadIdx.x, wid = tid >> 5, lane = tid & 31;
    int* sTok = (int*)(smem + 2 * G1_STG);

    if (tid < 128) {
        int m = mBase + tid;
        sTok[tid] = (m < n_rows) ? g_tok[e * Tn + m] : -1;
    }
    __syncthreads();

    const float* Wg_e = Wg + (size_t)e * Hn * In + n0;
    const float* Wu_e = Wu + (size_t)e * Hn * In + n0;

    int wm = wid & 3, wn = wid >> 2;
    int ar = lane & 15, ac = lane >> 4;
    int brow = (lane >> 4) * 8 + (lane & 7);
    int bhalf = (lane & 15) >> 3;

    int bn  = tid & 63;
    int bkq = tid >> 6;      // 0..7, each 4 k's
    int aRowT[2], aC4T[2];
    #pragma unroll
    for (int it = 0; it < 2; it++) {
        int idx = it * 512 + tid;
        aRowT[it] = idx >> 3;  aC4T[it] = idx & 7;
    }

    float4 rA[2];
    float rG[4], rU[4];

    // ---- reg-load / STS helpers (macros keep regs local) ----
    #define G1_LDG(k0)                                                         \
        do {                                                                   \
            _Pragma("unroll")                                                  \
            for (int it = 0; it < 2; it++) {                                   \
                int tok = sTok[aRowT[it]];                                     \
                rA[it] = (tok >= 0)                                            \
                    ? *(const float4*)(x + (size_t)tok * Hn + (k0) + aC4T[it] * 4) \
                    : make_float4(0.f, 0.f, 0.f, 0.f);                         \
            }                                                                  \
            _Pragma("unroll")                                                  \
            for (int j = 0; j < 4; j++) {                                      \
                size_t o = (size_t)((k0) + bkq * 4 + j) * In + bn;             \
                rG[j] = Wg_e[o];  rU[j] = Wu_e[o];                             \
            }                                                                  \
        } while (0)

    #define G1_STS(buf)                                                        \
        do {                                                                   \
            char* st = smem + (buf) * G1_STG;                                  \
            char* Ah = st;  char* Al = st + A_ARR;                             \
            _Pragma("unroll")                                                  \
            for (int it = 0; it < 2; it++) {                                   \
                uint32_t h0, l0, h1, l1;                                       \
                split2(rA[it].x, rA[it].y, h0, l0);                            \
                split2(rA[it].z, rA[it].w, h1, l1);                            \
                uint32_t off = aRowT[it] * ROWB + aC4T[it] * 8;                \
                *(uint2*)(Ah + off) = make_uint2(h0, h1);                      \
                *(uint2*)(Al + off) = make_uint2(l0, l1);                      \
            }                                                                  \
            char* Gh = st + 2 * A_ARR;                                         \
            uint32_t gh[2], gl[2], uh[2], ul[2];                               \
            split2(rG[0], rG[1], gh[0], gl[0]);                                \
            split2(rG[2], rG[3], gh[1], gl[1]);                                \
            split2(rU[0], rU[1], uh[0], ul[0]);                                \
            split2(rU[2], rU[3], uh[1], ul[1]);                                \
            uint32_t boff = bn * ROWB + bkq * 8;                               \
            *(uint2*)(Gh + boff)             = make_uint2(gh[0], gh[1]);       \
            *(uint2*)(Gh + B_ARR + boff)     = make_uint2(gl[0], gl[1]);       \
            *(uint2*)(Gh + 2 * B_ARR + boff) = make_uint2(uh[0], uh[1]);       \
            *(uint2*)(Gh + 3 * B_ARR + boff) = make_uint2(ul[0], ul[1]);       \
        } while (0)

    float aG[2][2][4] = {{{0}}}, aU[2][2][4] = {{{0}}};

    // prologue: LDG(0) -> STS buf0 -> LDG(1) -> sync
    G1_LDG(0);
    G1_STS(0);
    G1_LDG(32);
    __syncthreads();

    #pragma unroll 1
    for (int s = 0; s < 32; s++) {
        // compute stage s from buf s&1
        uint32_t aBase = sb + (s & 1) * G1_STG;
        uint32_t gBase = aBase + 2 * A_ARR;
        #pragma unroll
        for (int kk = 0; kk < 2; kk++) {
            int kb = kk * 32;
            uint32_t ah[2][4], al[2][4];
            #pragma unroll
            for (int mt = 0; mt < 2; mt++) {
                uint32_t ad = aBase + (uint32_t)(wm * 32 + mt * 16 + ar) * ROWB + kb + ac * 16;
                LDM4(ah[mt], ad);
                LDM4(al[mt], ad + A_ARR);
            }
            uint32_t bgh[4], bgl[4], buh[4], bul[4];
            {
                uint32_t bd = gBase + (uint32_t)(wn * 16 + brow) * ROWB + kb + bhalf * 16;
                LDM4(bgh, bd);
                LDM4(bgl, bd + B_ARR);
                LDM4(buh, bd + 2 * B_ARR);
                LDM4(bul, bd + 3 * B_ARR);
            }
            #pragma unroll
            for (int mt = 0; mt < 2; mt++)
                #pragma unroll
                for (int nt = 0; nt < 2; nt++) {
                    int p = nt * 2;
                    MMA(aG[mt][nt], ah[mt], bgh[p], bgh[p + 1]);
                    MMA(aU[mt][nt], ah[mt], buh[p], buh[p + 1]);
                }
            #pragma unroll
            for (int mt = 0; mt < 2; mt++)
                #pragma unroll
                for (int nt = 0; nt < 2; nt++) {
                    int p = nt * 2;
                    MMA(aG[mt][nt], ah[mt], bgl[p], bgl[p + 1]);
                    MMA(aU[mt][nt], ah[mt], bul[p], bul[p + 1]);
                }
            #pragma unroll
            for (int mt = 0; mt < 2; mt++)
                #pragma unroll
                for (int nt = 0; nt < 2; nt++) {
                    int p = nt * 2;
                    MMA(aG[mt][nt], al[mt], bgh[p], bgh[p + 1]);
                    MMA(aU[mt][nt], al[mt], buh[p], buh[p + 1]);
                }
        }
        // store-behind: regs hold stage s+1; write into buf (s+1)&1
        if (s < 31) {
            G1_STS((s + 1) & 1);
            if (s < 30) G1_LDG((s + 2) * 32);
        }
        __syncthreads();
    }

    // epilogue
    #pragma unroll
    for (int mt = 0; mt < 2; mt++) {
        #pragma unroll
        for (int nt = 0; nt < 2; nt++) {
            int c = n0 + wn * 16 + nt * 8 + (lane & 3) * 2;
            #pragma unroll
            for (int h = 0; h < 2; h++) {
                int r = mBase + wm * 32 + mt * 16 + (lane >> 2) + h * 8;
                if (r < n_rows) {
                    float g0 = aG[mt][nt][h * 2],     u0 = aU[mt][nt][h * 2];
                    float g1 = aG[mt][nt][h * 2 + 1], u1 = aU[mt][nt][h * 2 + 1];
                    float i0 = u0 * g0 / (1.0f + __expf(-g0));
                    float i1 = u1 * g1 / (1.0f + __expf(-g1));
                    uint32_t ph, pl;
                    split2(i0, i1, ph, pl);
                    size_t o = ((size_t)e * Tn + r) * In + c;
                    *(uint32_t*)(g_ih + o) = ph;
                    *(uint32_t*)(g_il + o) = pl;
                }
            }
        }
    }
    #undef G1_LDG
    #undef G1_STS
}

// ==================== GEMM2: CTA 128x128, 16 warps 4x4, warp 32x32 ====================
__global__ __launch_bounds__(512, 1)
void gemm2_kernel(const float* __restrict__ Wd) {
    extern __shared__ char smem[];
    int e = blockIdx.z;
    int n_rows = g_cnt[e];
    int mBase = blockIdx.y * 128;
    if (mBase >= n_rows) return;
    int n0 = blockIdx.x * 128;

    uint32_t sb = smem_u32(smem);
    int tid = threadIdx.x, wid = tid >> 5, lane = tid & 31;
    int wm = wid & 3, wn = wid >> 2;
    int ar = lane & 15, ac = lane >> 4;
    int brow = (lane >> 4) * 8 + (lane & 7);
    int bhalf = (lane & 15) >> 3;

    const __nv_bfloat16* Ah_g = g_ih + ((size_t)(e * Tn + mBase)) * In;
    const __nv_bfloat16* Al_g = g_il + ((size_t)(e * Tn + mBase)) * In;
    const float* Bw = Wd + (size_t)e * In * Hn + n0;

    int arow = tid >> 2, ach = tid & 3;   // A: 128 rows x 4 chunks of 16B
    int bn = tid & 127, bq = tid >> 7;    // B: 128 n x 4 k-groups of 8

    uint4 rAh, rAl;
    float rB[8];

    #define G2_LDG(k0)                                                         \
        do {                                                                   \
            rAh = *(const uint4*)(Ah_g + (size_t)arow * In + (k0) + ach * 8);  \
            rAl = *(const uint4*)(Al_g + (size_t)arow * In + (k0) + ach * 8);  \
            _Pragma("unroll")                                                  \
            for (int j = 0; j < 8; j++)                                        \
                rB[j] = Bw[(size_t)((k0) + bq * 8 + j) * Hn + bn];             \
        } while (0)

    #define G2_STS(buf)                                                        \
        do {                                                                   \
            char* st = smem + (buf) * G2_STG;                                  \
            uint32_t off = arow * ROWB + ach * 16;                             \
            *(uint4*)(st + off)         = rAh;                                 \
            *(uint4*)(st + A_ARR + off) = rAl;                                 \
            char* Bh = st + 2 * A_ARR;                                         \
            uint32_t bh[4], bl[4];                                             \
            _Pragma("unroll")                                                  \
            for (int j = 0; j < 4; j++)                                        \
                split2(rB[2 * j], rB[2 * j + 1], bh[j], bl[j]);                \
            uint32_t boff = bn * ROWB + bq * 16;                               \
            *(uint4*)(Bh + boff)          = make_uint4(bh[0], bh[1], bh[2], bh[3]); \
            *(uint4*)(Bh + B2_ARR + boff) = make_uint4(bl[0], bl[1], bl[2], bl[3]); \
        } while (0)

    float acc[2][4][4] = {{{0}}};

    G2_LDG(0);
    G2_STS(0);
    G2_LDG(32);
    __syncthreads();

    #pragma unroll 1
    for (int s = 0; s < 32; s++) {
        uint32_t aBase = sb + (s & 1) * G2_STG;
        uint32_t bBase = aBase + 2 * A_ARR;
        #pragma unroll
        for (int kk = 0; kk < 2; kk++) {
            int kb = kk * 32;
            uint32_t ah[2][4], al[2][4];
            #pragma unroll
            for (int mt = 0; mt < 2; mt++) {
                uint32_t ad = aBase + (uint32_t)(wm * 32 + mt * 16 + ar) * ROWB + kb + ac * 16;
                LDM4(ah[mt], ad);
                LDM4(al[mt], ad + A_ARR);
            }
            uint32_t bh[2][4], bl[2][4];
            #pragma unroll
            for (int ng = 0; ng < 2; ng++) {
                uint32_t bd = bBase + (uint32_t)(wn * 32 + ng * 16 + brow) * ROWB + kb + bhalf * 16;
                LDM4(bh[ng], bd);
                LDM4(bl[ng], bd + B2_ARR);
            }
            #pragma unroll
            for (int mt = 0; mt < 2; mt++)
                #pragma unroll
                for (int nt = 0; nt < 4; nt++) {
                    int ng = nt >> 1, p = (nt & 1) * 2;
                    MMA(acc[mt][nt], ah[mt], bh[ng][p], bh[ng][p + 1]);
                }
            #pragma unroll
            for (int mt = 0; mt < 2; mt++)
                #pragma unroll
                for (int nt = 0; nt < 4; nt++) {
                    int ng = nt >> 1, p = (nt & 1) * 2;
                    MMA(acc[mt][nt], ah[mt], bl[ng][p], bl[ng][p + 1]);
                }
            #pragma unroll
            for (int mt = 0; mt < 2; mt++)
                #pragma unroll
                for (int nt = 0; nt < 4; nt++) {
                    int ng = nt >> 1, p = (nt & 1) * 2;
                    MMA(acc[mt][nt], al[mt], bh[ng][p], bh[ng][p + 1]);
                }
        }
        if (s < 31) {
            G2_STS((s + 1) & 1);
            if (s < 30) G2_LDG((s + 2) * 32);
        }
        __syncthreads();
    }

    #pragma unroll
    for (int mt = 0; mt < 2; mt++) {
        #pragma unroll
        for (int nt = 0; nt < 4; nt++) {
            int c = n0 + wn * 32 + nt * 8 + (lane & 3) * 2;
            #pragma unroll
            for (int h = 0; h < 2; h++) {
                int r = mBase + wm * 32 + mt * 16 + (lane >> 2) + h * 8;
                if (r < n_rows)
                    *(float2*)(g_out2 + ((size_t)e * Tn + r) * Hn + c) =
                        make_float2(acc[mt][nt][h * 2], acc[mt][nt][h * 2 + 1]);
            }
        }
    }
    #undef G2_LDG
    #undef G2_STS
}

// ==================== launch ====================
extern "C" void kernel_launch(void* const* d_in, const int* in_sizes, int n_in,
                              void* d_out, int out_size) {
    const float* x  = (const float*)d_in[0];
    const float* Wr = (const float*)d_in[1];
    const float* Wg = (const float*)d_in[2];
    const float* Wu = (const float*)d_in[3];
    const float* Wd = (const float*)d_in[4];
    float* out = (float*)d_out;

    cudaFuncSetAttribute(gemm1_kernel, cudaFuncAttributeMaxDynamicSharedMemorySize, G1_SMEM);
    cudaFuncSetAttribute(gemm2_kernel, cudaFuncAttributeMaxDynamicSharedMemorySize, G2_SMEM);

    init_kernel<<<1, 32>>>();
    router_kernel<<<Tn, 256>>>(x, Wr);
    if (out_size > Tn * Hn)
        aux_kernel<<<1, 32>>>(out, Tn * Hn);

    dim3 g1(In / 64, Tn / 128, En);
    gemm1_kernel<<<g1, 512, G1_SMEM>>>(x, Wg, Wu);

    dim3 g2(Hn / 128, Tn / 128, En);
    gemm2_kernel<<<g2, 512, G2_SMEM>>>(Wd);

    combine_kernel<<<Tn, 256>>>(out);
}

// round 8
// speedup vs baseline: 1.4976x; 1.2971x over previous
#include <cuda_runtime.h>
#include <cuda_fp16.h>
#include <stdint.h>
#include <math.h>

#define Tn 4096
#define Hn 1024
#define En 8
#define In 1024

// ==================== scratch ====================
__device__ int   g_cnt[En];
__device__ float g_imp[En];
__device__ int   g_tok[En * Tn];
__device__ int   g_tk [Tn * 2];
__device__ float g_tkw[Tn * 2];
__device__ __half g_ih[(size_t)En * Tn * In], g_il[(size_t)En * Tn * In];
__device__ float g_out2[(size_t)En * Tn * Hn];

// ==================== helpers ====================
__device__ __forceinline__ uint32_t smem_u32(const void* p) {
    uint32_t a;
    asm("{ .reg .u64 t; cvta.to.shared.u64 t, %1; cvt.u32.u64 %0, t; }" : "=r"(a) : "l"(p));
    return a;
}

#define LDM4(r, addr)                                                          \
    asm volatile("ldmatrix.sync.aligned.m8n8.x4.shared.b16 {%0,%1,%2,%3}, [%4];" \
        : "=r"((r)[0]), "=r"((r)[1]), "=r"((r)[2]), "=r"((r)[3]) : "r"(addr))

#define MMA(d, a, b0, b1)                                                      \
    asm volatile("mma.sync.aligned.m16n8k16.row.col.f32.f16.f16.f32 "          \
        "{%0,%1,%2,%3}, {%4,%5,%6,%7}, {%8,%9}, {%0,%1,%2,%3};"                \
        : "+f"((d)[0]), "+f"((d)[1]), "+f"((d)[2]), "+f"((d)[3])               \
        : "r"((a)[0]), "r"((a)[1]), "r"((a)[2]), "r"((a)[3]), "r"(b0), "r"(b1))

// fp16 split: a = hi + lo to ~2^-22
__device__ __forceinline__ void split2h(float a, float b, uint32_t& hi, uint32_t& lo) {
    __half ha = __float2half_rn(a), hb = __float2half_rn(b);
    float ra = a - __half2float(ha), rb = b - __half2float(hb);
    __half2 H = __halves2half2(ha, hb);
    __half2 L = __floats2half2_rn(ra, rb);
    hi = *(uint32_t*)&H;  lo = *(uint32_t*)&L;
}
__device__ __forceinline__ uint32_t pack2h(float a, float b) {
    __half2 H = __floats2half2_rn(a, b);
    return *(uint32_t*)&H;
}

// ==================== small kernels ====================
__global__ void init_kernel() {
    if (threadIdx.x < En) { g_cnt[threadIdx.x] = 0; g_imp[threadIdx.x] = 0.0f; }
}

__global__ void router_kernel(const float* __restrict__ x, const float* __restrict__ Wr) {
    int t = blockIdx.x;
    int warp = threadIdx.x >> 5, lane = threadIdx.x & 31;
    const float* xt = x + (size_t)t * Hn;
    float acc = 0.0f;
    for (int h = lane; h < Hn; h += 32) acc += xt[h] * Wr[h * En + warp];
    #pragma unroll
    for (int o = 16; o > 0; o >>= 1) acc += __shfl_xor_sync(0xffffffff, acc, o);
    __shared__ float logits[En];
    if (lane == 0) logits[warp] = acc;
    __syncthreads();
    if (threadIdx.x == 0) {
        float mx = logits[0];
        #pragma unroll
        for (int e = 1; e < En; e++) mx = fmaxf(mx, logits[e]);
        float p[En], s = 0.0f;
        #pragma unroll
        for (int e = 0; e < En; e++) { p[e] = expf(logits[e] - mx); s += p[e]; }
        float inv = 1.0f / s;
        #pragma unroll
        for (int e = 0; e < En; e++) { p[e] *= inv; atomicAdd(&g_imp[e], p[e]); }
        int i0 = 0;
        #pragma unroll
        for (int e = 1; e < En; e++) if (p[e] > p[i0]) i0 = e;
        int i1 = (i0 == 0) ? 1 : 0;
        #pragma unroll
        for (int e = 0; e < En; e++) if (e != i0 && p[e] > p[i1]) i1 = e;
        float w0 = p[i0], w1 = p[i1];
        float sw = fmaxf(w0 + w1, 1e-9f);
        w0 /= sw; w1 /= sw;
        int p0 = atomicAdd(&g_cnt[i0], 1);
        int p1 = atomicAdd(&g_cnt[i1], 1);
        g_tok[i0 * Tn + p0] = t;
        g_tok[i1 * Tn + p1] = t;
        g_tk [t * 2]     = i0 * Tn + p0;  g_tkw[t * 2]     = w0;
        g_tk [t * 2 + 1] = i1 * Tn + p1;  g_tkw[t * 2 + 1] = w1;
    }
}

__global__ void aux_kernel(float* out, int aux_idx) {
    if (threadIdx.x == 0) {
        float s = 0.0f;
        #pragma unroll
        for (int e = 0; e < En; e++)
            s += ((float)g_cnt[e] / (float)Tn) * (g_imp[e] / (float)Tn);
        out[aux_idx] = (float)En * s * 0.01f;
    }
}

__global__ void combine_kernel(float* __restrict__ out) {
    int t = blockIdx.x;
    int s0 = g_tk[2 * t], s1 = g_tk[2 * t + 1];
    float w0 = g_tkw[2 * t], w1 = g_tkw[2 * t + 1];
    const float4* a = (const float4*)(g_out2 + (size_t)s0 * Hn);
    const float4* b = (const float4*)(g_out2 + (size_t)s1 * Hn);
    float4* o = (float4*)(out + (size_t)t * Hn);
    int i = threadIdx.x;
    float4 va = a[i], vb = b[i];
    o[i] = make_float4(w0 * va.x + w1 * vb.x, w0 * va.y + w1 * vb.y,
                       w0 * va.z + w1 * vb.z, w0 * va.w + w1 * vb.w);
}

// ==================== smem layout ====================
#define ROWB 80
#define A_ARR 10240             // 128 rows * 80B
#define B_ARR 5120              // 64 rows * 80B
#define B2_ARR 10240            // 128 rows * 80B (gemm2 B)
#define G1_STG (2 * A_ARR + 2 * B_ARR)   // Ah Al Gh Uh = 30720
#define G1_SMEM (2 * G1_STG + 512)
#define G2_STG (2 * A_ARR + B2_ARR)      // Ah Al Bh = 30720
#define G2_SMEM (2 * G2_STG)

// ==================== GEMM1: CTA 128x64(G)+64(U), 16 warps 4x4, warp 32x16 ====================
__global__ __launch_bounds__(512, 1)
void gemm1_kernel(const float* __restrict__ x,
                  const float* __restrict__ Wg,
                  const float* __restrict__ Wu) {
    extern __shared__ char smem[];
    int e = blockIdx.z;
    int n_rows = g_cnt[e];
    int mBase = blockIdx.y * 128;
    if (mBase >= n_rows) return;
    int n0 = blockIdx.x * 64;

    uint32_t sb = smem_u32(smem);
    int tid = threadIdx.x, wid = tid >> 5, lane = tid & 31;
    int* sTok = (int*)(smem + 2 * G1_STG);

    if (tid < 128) {
        int m = mBase + tid;
        sTok[tid] = (m < n_rows) ? g_tok[e * Tn + m] : -1;
    }
    __syncthreads();

    const float* Wg_e = Wg + (size_t)e * Hn * In + n0;
    const float* Wu_e = Wu + (size_t)e * Hn * In + n0;

    int wm = wid & 3, wn = wid >> 2;
    int ar = lane & 15, ac = lane >> 4;
    int brow = (lane >> 4) * 8 + (lane & 7);
    int bhalf = (lane & 15) >> 3;

    int bn  = tid & 63;
    int bkq = tid >> 6;      // 0..7, each 4 k's
    int aRowT[2], aC4T[2];
    #pragma unroll
    for (int it = 0; it < 2; it++) {
        int idx = it * 512 + tid;
        aRowT[it] = idx >> 3;  aC4T[it] = idx & 7;
    }

    float4 rA[2];
    float rG[4], rU[4];

    #define G1_LDG(k0)                                                         \
        do {                                                                   \
            _Pragma("unroll")                                                  \
            for (int it = 0; it < 2; it++) {                                   \
                int tok = sTok[aRowT[it]];                                     \
                rA[it] = (tok >= 0)                                            \
                    ? *(const float4*)(x + (size_t)tok * Hn + (k0) + aC4T[it] * 4) \
                    : make_float4(0.f, 0.f, 0.f, 0.f);                         \
            }                                                                  \
            _Pragma("unroll")                                                  \
            for (int j = 0; j < 4; j++) {                                      \
                size_t o = (size_t)((k0) + bkq * 4 + j) * In + bn;             \
                rG[j] = Wg_e[o];  rU[j] = Wu_e[o];                             \
            }                                                                  \
        } while (0)

    #define G1_STS(buf)                                                        \
        do {                                                                   \
            char* st = smem + (buf) * G1_STG;                                  \
            char* Ah = st;  char* Al = st + A_ARR;                             \
            _Pragma("unroll")                                                  \
            for (int it = 0; it < 2; it++) {                                   \
                uint32_t h0, l0, h1, l1;                                       \
                split2h(rA[it].x, rA[it].y, h0, l0);                           \
                split2h(rA[it].z, rA[it].w, h1, l1);                           \
                uint32_t off = aRowT[it] * ROWB + aC4T[it] * 8;                \
                *(uint2*)(Ah + off) = make_uint2(h0, h1);                      \
                *(uint2*)(Al + off) = make_uint2(l0, l1);                      \
            }                                                                  \
            char* Gh = st + 2 * A_ARR;                                         \
            uint32_t gh0 = pack2h(rG[0], rG[1]), gh1 = pack2h(rG[2], rG[3]);   \
            uint32_t uh0 = pack2h(rU[0], rU[1]), uh1 = pack2h(rU[2], rU[3]);   \
            uint32_t boff = bn * ROWB + bkq * 8;                               \
            *(uint2*)(Gh + boff)         = make_uint2(gh0, gh1);               \
            *(uint2*)(Gh + B_ARR + boff) = make_uint2(uh0, uh1);               \
        } while (0)

    float aG[2][2][4] = {{{0}}}, aU[2][2][4] = {{{0}}};

    G1_LDG(0);
    G1_STS(0);
    G1_LDG(32);
    __syncthreads();

    #pragma unroll 1
    for (int s = 0; s < 32; s++) {
        uint32_t aBase = sb + (s & 1) * G1_STG;
        uint32_t gBase = aBase + 2 * A_ARR;
        #pragma unroll
        for (int kk = 0; kk < 2; kk++) {
            int kb = kk * 32;
            uint32_t ah[2][4], al[2][4];
            #pragma unroll
            for (int mt = 0; mt < 2; mt++) {
                uint32_t ad = aBase + (uint32_t)(wm * 32 + mt * 16 + ar) * ROWB + kb + ac * 16;
                LDM4(ah[mt], ad);
                LDM4(al[mt], ad + A_ARR);
            }
            uint32_t bg[4], bu[4];
            {
                uint32_t bd = gBase + (uint32_t)(wn * 16 + brow) * ROWB + kb + bhalf * 16;
                LDM4(bg, bd);
                LDM4(bu, bd + B_ARR);
            }
            // pass 1: ah * B
            #pragma unroll
            for (int mt = 0; mt < 2; mt++)
                #pragma unroll
                for (int nt = 0; nt < 2; nt++) {
                    int p = nt * 2;
                    MMA(aG[mt][nt], ah[mt], bg[p], bg[p + 1]);
                    MMA(aU[mt][nt], ah[mt], bu[p], bu[p + 1]);
                }
            // pass 2: al * B
            #pragma unroll
            for (int mt = 0; mt < 2; mt++)
                #pragma unroll
                for (int nt = 0; nt < 2; nt++) {
                    int p = nt * 2;
                    MMA(aG[mt][nt], al[mt], bg[p], bg[p + 1]);
                    MMA(aU[mt][nt], al[mt], bu[p], bu[p + 1]);
                }
        }
        if (s < 31) {
            G1_STS((s + 1) & 1);
            if (s < 30) G1_LDG((s + 2) * 32);
        }
        __syncthreads();
    }

    // epilogue: silu(g)*u -> split fp16 intermediate
    #pragma unroll
    for (int mt = 0; mt < 2; mt++) {
        #pragma unroll
        for (int nt = 0; nt < 2; nt++) {
            int c = n0 + wn * 16 + nt * 8 + (lane & 3) * 2;
            #pragma unroll
            for (int h = 0; h < 2; h++) {
                int r = mBase + wm * 32 + mt * 16 + (lane >> 2) + h * 8;
                if (r < n_rows) {
                    float g0 = aG[mt][nt][h * 2],     u0 = aU[mt][nt][h * 2];
                    float g1 = aG[mt][nt][h * 2 + 1], u1 = aU[mt][nt][h * 2 + 1];
                    float i0 = u0 * g0 / (1.0f + __expf(-g0));
                    float i1 = u1 * g1 / (1.0f + __expf(-g1));
                    uint32_t ph, pl;
                    split2h(i0, i1, ph, pl);
                    size_t o = ((size_t)e * Tn + r) * In + c;
                    *(uint32_t*)(g_ih + o) = ph;
                    *(uint32_t*)(g_il + o) = pl;
                }
            }
        }
    }
    #undef G1_LDG
    #undef G1_STS
}

// ==================== GEMM2: CTA 128x128, 16 warps 4x4, warp 32x32 ====================
__global__ __launch_bounds__(512, 1)
void gemm2_kernel(const float* __restrict__ Wd) {
    extern __shared__ char smem[];
    int e = blockIdx.z;
    int n_rows = g_cnt[e];
    int mBase = blockIdx.y * 128;
    if (mBase >= n_rows) return;
    int n0 = blockIdx.x * 128;

    uint32_t sb = smem_u32(smem);
    int tid = threadIdx.x, wid = tid >> 5, lane = tid & 31;
    int wm = wid & 3, wn = wid >> 2;
    int ar = lane & 15, ac = lane >> 4;
    int brow = (lane >> 4) * 8 + (lane & 7);
    int bhalf = (lane & 15) >> 3;

    const __half* Ah_g = g_ih + ((size_t)(e * Tn + mBase)) * In;
    const __half* Al_g = g_il + ((size_t)(e * Tn + mBase)) * In;
    const float* Bw = Wd + (size_t)e * In * Hn + n0;

    int arow = tid >> 2, ach = tid & 3;
    int bn = tid & 127, bq = tid >> 7;

    uint4 rAh, rAl;
    float rB[8];

    #define G2_LDG(k0)                                                         \
        do {                                                                   \
            rAh = *(const uint4*)(Ah_g + (size_t)arow * In + (k0) + ach * 8);  \
            rAl = *(const uint4*)(Al_g + (size_t)arow * In + (k0) + ach * 8);  \
            _Pragma("unroll")                                                  \
            for (int j = 0; j < 8; j++)                                        \
                rB[j] = Bw[(size_t)((k0) + bq * 8 + j) * Hn + bn];             \
        } while (0)

    #define G2_STS(buf)                                                        \
        do {                                                                   \
            char* st = smem + (buf) * G2_STG;                                  \
            uint32_t off = arow * ROWB + ach * 16;                             \
            *(uint4*)(st + off)         = rAh;                                 \
            *(uint4*)(st + A_ARR + off) = rAl;                                 \
            char* Bh = st + 2 * A_ARR;                                         \
            uint32_t b0 = pack2h(rB[0], rB[1]), b1 = pack2h(rB[2], rB[3]);     \
            uint32_t b2 = pack2h(rB[4], rB[5]), b3 = pack2h(rB[6], rB[7]);     \
            uint32_t boff = bn * ROWB + bq * 16;                               \
            *(uint4*)(Bh + boff) = make_uint4(b0, b1, b2, b3);                 \
        } while (0)

    float acc[2][4][4] = {{{0}}};

    G2_LDG(0);
    G2_STS(0);
    G2_LDG(32);
    __syncthreads();

    #pragma unroll 1
    for (int s = 0; s < 32; s++) {
        uint32_t aBase = sb + (s & 1) * G2_STG;
        uint32_t bBase = aBase + 2 * A_ARR;
        #pragma unroll
        for (int kk = 0; kk < 2; kk++) {
            int kb = kk * 32;
            uint32_t ah[2][4], al[2][4];
            #pragma unroll
            for (int mt = 0; mt < 2; mt++) {
                uint32_t ad = aBase + (uint32_t)(wm * 32 + mt * 16 + ar) * ROWB + kb + ac * 16;
                LDM4(ah[mt], ad);
                LDM4(al[mt], ad + A_ARR);
            }
            uint32_t bh[2][4];
            #pragma unroll
            for (int ng = 0; ng < 2; ng++) {
                uint32_t bd = bBase + (uint32_t)(wn * 32 + ng * 16 + brow) * ROWB + kb + bhalf * 16;
                LDM4(bh[ng], bd);
            }
            #pragma unroll
            for (int mt = 0; mt < 2; mt++)
                #pragma unroll
                for (int nt = 0; nt < 4; nt++) {
                    int ng = nt >> 1, p = (nt & 1) * 2;
                    MMA(acc[mt][nt], ah[mt], bh[ng][p], bh[ng][p + 1]);
                }
            #pragma unroll
            for (int mt = 0; mt < 2; mt++)
                #pragma unroll
                for (int nt = 0; nt < 4; nt++) {
                    int ng = nt >> 1, p = (nt & 1) * 2;
                    MMA(acc[mt][nt], al[mt], bh[ng][p], bh[ng][p + 1]);
                }
        }
        if (s < 31) {
            G2_STS((s + 1) & 1);
            if (s < 30) G2_LDG((s + 2) * 32);
        }
        __syncthreads();
    }

    #pragma unroll
    for (int mt = 0; mt < 2; mt++) {
        #pragma unroll
        for (int nt = 0; nt < 4; nt++) {
            int c = n0 + wn * 32 + nt * 8 + (lane & 3) * 2;
            #pragma unroll
            for (int h = 0; h < 2; h++) {
                int r = mBase + wm * 32 + mt * 16 + (lane >> 2) + h * 8;
                if (r < n_rows)
                    *(float2*)(g_out2 + ((size_t)e * Tn + r) * Hn + c) =
                        make_float2(acc[mt][nt][h * 2], acc[mt][nt][h * 2 + 1]);
            }
        }
    }
    #undef G2_LDG
    #undef G2_STS
}

// ==================== launch ====================
extern "C" void kernel_launch(void* const* d_in, const int* in_sizes, int n_in,
                              void* d_out, int out_size) {
    const float* x  = (const float*)d_in[0];
    const float* Wr = (const float*)d_in[1];
    const float* Wg = (const float*)d_in[2];
    const float* Wu = (const float*)d_in[3];
    const float* Wd = (const float*)d_in[4];
    float* out = (float*)d_out;

    cudaFuncSetAttribute(gemm1_kernel, cudaFuncAttributeMaxDynamicSharedMemorySize, G1_SMEM);
    cudaFuncSetAttribute(gemm2_kernel, cudaFuncAttributeMaxDynamicSharedMemorySize, G2_SMEM);

    init_kernel<<<1, 32>>>();
    router_kernel<<<Tn, 256>>>(x, Wr);
    if (out_size > Tn * Hn)
        aux_kernel<<<1, 32>>>(out, Tn * Hn);

    dim3 g1(In / 64, Tn / 128, En);
    gemm1_kernel<<<g1, 512, G1_SMEM>>>(x, Wg, Wu);

    dim3 g2(Hn / 128, Tn / 128, En);
    gemm2_kernel<<<g2, 512, G2_SMEM>>>(Wd);

    combine_kernel<<<Tn, 256>>>(out);
}

// round 9
// speedup vs baseline: 2.0501x; 1.3690x over previous
#include <cuda_runtime.h>
#include <cuda_fp16.h>
#include <stdint.h>
#include <math.h>

#define Tn 4096
#define Hn 1024
#define En 8
#define In 1024

// ==================== scratch ====================
__device__ int   g_cnt[En];
__device__ float g_imp[En];
__device__ int   g_tok[En * Tn];
__device__ int   g_tk [Tn * 2];
__device__ float g_tkw[Tn * 2];
__device__ __half g_ih[(size_t)En * Tn * In];    // fp16 intermediate
__device__ float g_out2[(size_t)En * Tn * Hn];

// ==================== helpers ====================
__device__ __forceinline__ uint32_t smem_u32(const void* p) {
    uint32_t a;
    asm("{ .reg .u64 t; cvta.to.shared.u64 t, %1; cvt.u32.u64 %0, t; }" : "=r"(a) : "l"(p));
    return a;
}

#define LDM4(r, addr)                                                          \
    asm volatile("ldmatrix.sync.aligned.m8n8.x4.shared.b16 {%0,%1,%2,%3}, [%4];" \
        : "=r"((r)[0]), "=r"((r)[1]), "=r"((r)[2]), "=r"((r)[3]) : "r"(addr))

#define MMA(d, a, b0, b1)                                                      \
    asm volatile("mma.sync.aligned.m16n8k16.row.col.f32.f16.f16.f32 "          \
        "{%0,%1,%2,%3}, {%4,%5,%6,%7}, {%8,%9}, {%0,%1,%2,%3};"                \
        : "+f"((d)[0]), "+f"((d)[1]), "+f"((d)[2]), "+f"((d)[3])               \
        : "r"((a)[0]), "r"((a)[1]), "r"((a)[2]), "r"((a)[3]), "r"(b0), "r"(b1))

__device__ __forceinline__ uint32_t pack2h(float a, float b) {
    __half2 H = __floats2half2_rn(a, b);
    return *(uint32_t*)&H;
}

// ==================== small kernels ====================
__global__ void init_kernel() {
    if (threadIdx.x < En) { g_cnt[threadIdx.x] = 0; g_imp[threadIdx.x] = 0.0f; }
}

__global__ void router_kernel(const float* __restrict__ x, const float* __restrict__ Wr) {
    int t = blockIdx.x;
    int warp = threadIdx.x >> 5, lane = threadIdx.x & 31;
    const float* xt = x + (size_t)t * Hn;
    float acc = 0.0f;
    for (int h = lane; h < Hn; h += 32) acc += xt[h] * Wr[h * En + warp];
    #pragma unroll
    for (int o = 16; o > 0; o >>= 1) acc += __shfl_xor_sync(0xffffffff, acc, o);
    __shared__ float logits[En];
    if (lane == 0) logits[warp] = acc;
    __syncthreads();
    if (threadIdx.x == 0) {
        float mx = logits[0];
        #pragma unroll
        for (int e = 1; e < En; e++) mx = fmaxf(mx, logits[e]);
        float p[En], s = 0.0f;
        #pragma unroll
        for (int e = 0; e < En; e++) { p[e] = expf(logits[e] - mx); s += p[e]; }
        float inv = 1.0f / s;
        #pragma unroll
        for (int e = 0; e < En; e++) { p[e] *= inv; atomicAdd(&g_imp[e], p[e]); }
        int i0 = 0;
        #pragma unroll
        for (int e = 1; e < En; e++) if (p[e] > p[i0]) i0 = e;
        int i1 = (i0 == 0) ? 1 : 0;
        #pragma unroll
        for (int e = 0; e < En; e++) if (e != i0 && p[e] > p[i1]) i1 = e;
        float w0 = p[i0], w1 = p[i1];
        float sw = fmaxf(w0 + w1, 1e-9f);
        w0 /= sw; w1 /= sw;
        int p0 = atomicAdd(&g_cnt[i0], 1);
        int p1 = atomicAdd(&g_cnt[i1], 1);
        g_tok[i0 * Tn + p0] = t;
        g_tok[i1 * Tn + p1] = t;
        g_tk [t * 2]     = i0 * Tn + p0;  g_tkw[t * 2]     = w0;
        g_tk [t * 2 + 1] = i1 * Tn + p1;  g_tkw[t * 2 + 1] = w1;
    }
}

__global__ void aux_kernel(float* out, int aux_idx) {
    if (threadIdx.x == 0) {
        float s = 0.0f;
        #pragma unroll
        for (int e = 0; e < En; e++)
            s += ((float)g_cnt[e] / (float)Tn) * (g_imp[e] / (float)Tn);
        out[aux_idx] = (float)En * s * 0.01f;
    }
}

__global__ void combine_kernel(float* __restrict__ out) {
    int t = blockIdx.x;
    int s0 = g_tk[2 * t], s1 = g_tk[2 * t + 1];
    float w0 = g_tkw[2 * t], w1 = g_tkw[2 * t + 1];
    const float4* a = (const float4*)(g_out2 + (size_t)s0 * Hn);
    const float4* b = (const float4*)(g_out2 + (size_t)s1 * Hn);
    float4* o = (float4*)(out + (size_t)t * Hn);
    int i = threadIdx.x;
    float4 va = a[i], vb = b[i];
    o[i] = make_float4(w0 * va.x + w1 * vb.x, w0 * va.y + w1 * vb.y,
                       w0 * va.z + w1 * vb.z, w0 * va.w + w1 * vb.w);
}

// ==================== smem layout ====================
#define ROWB 80
#define A_ARR 10240             // 128 rows * 80B
#define B_ARR 5120              // 64 rows * 80B
#define B2_ARR 10240            // 128 rows * 80B (gemm2 B)
#define G1_STG (A_ARR + 2 * B_ARR)     // A Gh Uh = 20480
#define G1_SMEM (2 * G1_STG + 512)
#define G2_STG (A_ARR + B2_ARR)        // A Bh = 20480
#define G2_SMEM (2 * G2_STG)

// ==================== GEMM1: CTA 128x64(G)+64(U), 16 warps 4x4, warp 32x16 ====================
__global__ __launch_bounds__(512, 1)
void gemm1_kernel(const float* __restrict__ x,
                  const float* __restrict__ Wg,
                  const float* __restrict__ Wu) {
    extern __shared__ char smem[];
    int e = blockIdx.z;
    int n_rows = g_cnt[e];
    int mBase = blockIdx.y * 128;
    if (mBase >= n_rows) return;
    int n0 = blockIdx.x * 64;

    uint32_t sb = smem_u32(smem);
    int tid = threadIdx.x, wid = tid >> 5, lane = tid & 31;
    int* sTok = (int*)(smem + 2 * G1_STG);

    if (tid < 128) {
        int m = mBase + tid;
        sTok[tid] = (m < n_rows) ? g_tok[e * Tn + m] : -1;
    }
    __syncthreads();

    const float* Wg_e = Wg + (size_t)e * Hn * In + n0;
    const float* Wu_e = Wu + (size_t)e * Hn * In + n0;

    int wm = wid & 3, wn = wid >> 2;
    int ar = lane & 15, ac = lane >> 4;
    int brow = (lane >> 4) * 8 + (lane & 7);
    int bhalf = (lane & 15) >> 3;

    int bn  = tid & 63;
    int bkq = tid >> 6;      // 0..7, each 4 k's
    int aRowT[2], aC4T[2];
    #pragma unroll
    for (int it = 0; it < 2; it++) {
        int idx = it * 512 + tid;
        aRowT[it] = idx >> 3;  aC4T[it] = idx & 7;
    }

    float4 rA[2];
    float rG[4], rU[4];

    #define G1_LDG(k0)                                                         \
        do {                                                                   \
            _Pragma("unroll")                                                  \
            for (int it = 0; it < 2; it++) {                                   \
                int tok = sTok[aRowT[it]];                                     \
                rA[it] = (tok >= 0)                                            \
                    ? *(const float4*)(x + (size_t)tok * Hn + (k0) + aC4T[it] * 4) \
                    : make_float4(0.f, 0.f, 0.f, 0.f);                         \
            }                                                                  \
            _Pragma("unroll")                                                  \
            for (int j = 0; j < 4; j++) {                                      \
                size_t o = (size_t)((k0) + bkq * 4 + j) * In + bn;             \
                rG[j] = Wg_e[o];  rU[j] = Wu_e[o];                             \
            }                                                                  \
        } while (0)

    #define G1_STS(buf)                                                        \
        do {                                                                   \
            char* st = smem + (buf) * G1_STG;                                  \
            _Pragma("unroll")                                                  \
            for (int it = 0; it < 2; it++) {                                   \
                uint32_t h0 = pack2h(rA[it].x, rA[it].y);                      \
                uint32_t h1 = pack2h(rA[it].z, rA[it].w);                      \
                uint32_t off = aRowT[it] * ROWB + aC4T[it] * 8;                \
                *(uint2*)(st + off) = make_uint2(h0, h1);                      \
            }                                                                  \
            char* Gh = st + A_ARR;                                             \
            uint32_t gh0 = pack2h(rG[0], rG[1]), gh1 = pack2h(rG[2], rG[3]);   \
            uint32_t uh0 = pack2h(rU[0], rU[1]), uh1 = pack2h(rU[2], rU[3]);   \
            uint32_t boff = bn * ROWB + bkq * 8;                               \
            *(uint2*)(Gh + boff)         = make_uint2(gh0, gh1);               \
            *(uint2*)(Gh + B_ARR + boff) = make_uint2(uh0, uh1);               \
        } while (0)

    float aG[2][2][4] = {{{0}}}, aU[2][2][4] = {{{0}}};

    G1_LDG(0);
    G1_STS(0);
    G1_LDG(32);
    __syncthreads();

    #pragma unroll 1
    for (int s = 0; s < 32; s++) {
        uint32_t aBase = sb + (s & 1) * G1_STG;
        uint32_t gBase = aBase + A_ARR;
        #pragma unroll
        for (int kk = 0; kk < 2; kk++) {
            int kb = kk * 32;
            uint32_t ah[2][4];
            #pragma unroll
            for (int mt = 0; mt < 2; mt++) {
                uint32_t ad = aBase + (uint32_t)(wm * 32 + mt * 16 + ar) * ROWB + kb + ac * 16;
                LDM4(ah[mt], ad);
            }
            uint32_t bg[4], bu[4];
            {
                uint32_t bd = gBase + (uint32_t)(wn * 16 + brow) * ROWB + kb + bhalf * 16;
                LDM4(bg, bd);
                LDM4(bu, bd + B_ARR);
            }
            #pragma unroll
            for (int mt = 0; mt < 2; mt++)
                #pragma unroll
                for (int nt = 0; nt < 2; nt++) {
                    int p = nt * 2;
                    MMA(aG[mt][nt], ah[mt], bg[p], bg[p + 1]);
                    MMA(aU[mt][nt], ah[mt], bu[p], bu[p + 1]);
                }
        }
        if (s < 31) {
            G1_STS((s + 1) & 1);
            if (s < 30) G1_LDG((s + 2) * 32);
        }
        __syncthreads();
    }

    // epilogue: silu(g)*u -> fp16 intermediate
    #pragma unroll
    for (int mt = 0; mt < 2; mt++) {
        #pragma unroll
        for (int nt = 0; nt < 2; nt++) {
            int c = n0 + wn * 16 + nt * 8 + (lane & 3) * 2;
            #pragma unroll
            for (int h = 0; h < 2; h++) {
                int r = mBase + wm * 32 + mt * 16 + (lane >> 2) + h * 8;
                if (r < n_rows) {
                    float g0 = aG[mt][nt][h * 2],     u0 = aU[mt][nt][h * 2];
                    float g1 = aG[mt][nt][h * 2 + 1], u1 = aU[mt][nt][h * 2 + 1];
                    float i0 = u0 * g0 / (1.0f + __expf(-g0));
                    float i1 = u1 * g1 / (1.0f + __expf(-g1));
                    size_t o = ((size_t)e * Tn + r) * In + c;
                    *(uint32_t*)(g_ih + o) = pack2h(i0, i1);
                }
            }
        }
    }
    #undef G1_LDG
    #undef G1_STS
}

// ==================== GEMM2: CTA 128x128, 16 warps 4x4, warp 32x32 ====================
__global__ __launch_bounds__(512, 1)
void gemm2_kernel(const float* __restrict__ Wd) {
    extern __shared__ char smem[];
    int e = blockIdx.z;
    int n_rows = g_cnt[e];
    int mBase = blockIdx.y * 128;
    if (mBase >= n_rows) return;
    int n0 = blockIdx.x * 128;

    uint32_t sb = smem_u32(smem);
    int tid = threadIdx.x, wid = tid >> 5, lane = tid & 31;
    int wm = wid & 3, wn = wid >> 2;
    int ar = lane & 15, ac = lane >> 4;
    int brow = (lane >> 4) * 8 + (lane & 7);
    int bhalf = (lane & 15) >> 3;

    const __half* Ah_g = g_ih + ((size_t)(e * Tn + mBase)) * In;
    const float* Bw = Wd + (size_t)e * In * Hn + n0;

    int arow = tid >> 2, ach = tid & 3;
    int bn = tid & 127, bq = tid >> 7;

    uint4 rAh;
    float rB[8];

    #define G2_LDG(k0)                                                         \
        do {                                                                   \
            rAh = *(const uint4*)(Ah_g + (size_t)arow * In + (k0) + ach * 8);  \
            _Pragma("unroll")                                                  \
            for (int j = 0; j < 8; j++)                                        \
                rB[j] = Bw[(size_t)((k0) + bq * 8 + j) * Hn + bn];             \
        } while (0)

    #define G2_STS(buf)                                                        \
        do {                                                                   \
            char* st = smem + (buf) * G2_STG;                                  \
            uint32_t off = arow * ROWB + ach * 16;                             \
            *(uint4*)(st + off) = rAh;                                         \
            char* Bh = st + A_ARR;                                             \
            uint32_t b0 = pack2h(rB[0], rB[1]), b1 = pack2h(rB[2], rB[3]);     \
            uint32_t b2 = pack2h(rB[4], rB[5]), b3 = pack2h(rB[6], rB[7]);     \
            uint32_t boff = bn * ROWB + bq * 16;                               \
            *(uint4*)(Bh + boff) = make_uint4(b0, b1, b2, b3);                 \
        } while (0)

    float acc[2][4][4] = {{{0}}};

    G2_LDG(0);
    G2_STS(0);
    G2_LDG(32);
    __syncthreads();

    #pragma unroll 1
    for (int s = 0; s < 32; s++) {
        uint32_t aBase = sb + (s & 1) * G2_STG;
        uint32_t bBase = aBase + A_ARR;
        #pragma unroll
        for (int kk = 0; kk < 2; kk++) {
            int kb = kk * 32;
            uint32_t ah[2][4];
            #pragma unroll
            for (int mt = 0; mt < 2; mt++) {
                uint32_t ad = aBase + (uint32_t)(wm * 32 + mt * 16 + ar) * ROWB + kb + ac * 16;
                LDM4(ah[mt], ad);
            }
            uint32_t bh[2][4];
            #pragma unroll
            for (int ng = 0; ng < 2; ng++) {
                uint32_t bd = bBase + (uint32_t)(wn * 32 + ng * 16 + brow) * ROWB + kb + bhalf * 16;
                LDM4(bh[ng], bd);
            }
            #pragma unroll
            for (int mt = 0; mt < 2; mt++)
                #pragma unroll
                for (int nt = 0; nt < 4; nt++) {
                    int ng = nt >> 1, p = (nt & 1) * 2;
                    MMA(acc[mt][nt], ah[mt], bh[ng][p], bh[ng][p + 1]);
                }
        }
        if (s < 31) {
            G2_STS((s + 1) & 1);
            if (s < 30) G2_LDG((s + 2) * 32);
        }
        __syncthreads();
    }

    #pragma unroll
    for (int mt = 0; mt < 2; mt++) {
        #pragma unroll
        for (int nt = 0; nt < 4; nt++) {
            int c = n0 + wn * 32 + nt * 8 + (lane & 3) * 2;
            #pragma unroll
            for (int h = 0; h < 2; h++) {
                int r = mBase + wm * 32 + mt * 16 + (lane >> 2) + h * 8;
                if (r < n_rows)
                    *(float2*)(g_out2 + ((size_t)e * Tn + r) * Hn + c) =
                        make_float2(acc[mt][nt][h * 2], acc[mt][nt][h * 2 + 1]);
            }
        }
    }
    #undef G2_LDG
    #undef G2_STS
}

// ==================== launch ====================
extern "C" void kernel_launch(void* const* d_in, const int* in_sizes, int n_in,
                              void* d_out, int out_size) {
    const float* x  = (const float*)d_in[0];
    const float* Wr = (const float*)d_in[1];
    const float* Wg = (const float*)d_in[2];
    const float* Wu = (const float*)d_in[3];
    const float* Wd = (const float*)d_in[4];
    float* out = (float*)d_out;

    cudaFuncSetAttribute(gemm1_kernel, cudaFuncAttributeMaxDynamicSharedMemorySize, G1_SMEM);
    cudaFuncSetAttribute(gemm2_kernel, cudaFuncAttributeMaxDynamicSharedMemorySize, G2_SMEM);

    init_kernel<<<1, 32>>>();
    router_kernel<<<Tn, 256>>>(x, Wr);
    if (out_size > Tn * Hn)
        aux_kernel<<<1, 32>>>(out, Tn * Hn);

    dim3 g1(In / 64, Tn / 128, En);
    gemm1_kernel<<<g1, 512, G1_SMEM>>>(x, Wg, Wu);

    dim3 g2(Hn / 128, Tn / 128, En);
    gemm2_kernel<<<g2, 512, G2_SMEM>>>(Wd);

    combine_kernel<<<Tn, 256>>>(out);
}